// round 5
// baseline (speedup 1.0000x reference)
#include <cuda_runtime.h>
#include <math.h>
#include <limits.h>

#define MAXT 700000
#define MAXRUNS 64
#define NWALK (2*MAXRUNS)
#define CANDW 2048
#define MAXPK 16384
#define MAXOPS 8192
#define MAXC 256
#define MAXW 400
#define GRID(n,b) (((n)+(b)-1)/(b))

__device__ float g_f0[MAXT];
__device__ float g_f0s[MAXT];
__device__ unsigned g_absbits;
__device__ int g_anygate;
__device__ unsigned g_minbits;
__device__ float g_median;
__device__ float g_factor32, g_mshift32;

__device__ int g_st0[MAXRUNS], g_en0[MAXRUNS], g_st1[MAXRUNS], g_en1[MAXRUNS];
__device__ int g_cs0, g_ce0, g_cs1, g_ce1;
__device__ int g_runL0[MAXRUNS], g_runR0[MAXRUNS], g_nruns0;
__device__ int g_runL1[MAXRUNS], g_runR1[MAXRUNS], g_nruns1;
__device__ int g_tail, g_copy;
__device__ int g_backup[MAXRUNS];

__device__ int g_wci[NWALK*CANDW];
__device__ int g_wcnt[NWALK];
__device__ int g_lastApp[MAXRUNS];
__device__ double g_AR[MAXRUNS];

__device__ int g_cand[MAXPK];
__device__ int g_ncand, g_npk;
__device__ int g_peaks[MAXPK];

__device__ int g_opd[MAXOPS], g_opsrc[MAXOPS], g_opl[MAXOPS], g_opn[MAXOPS];
__device__ int g_nops;

__device__ __forceinline__ int pyslen(long start, long stop, long n) {
    if (start < 0) start += n; if (start < 0) start = 0; if (start > n) start = n;
    if (stop  < 0) stop  += n; if (stop  < 0) stop  = 0; if (stop  > n) stop  = n;
    long L = stop - start; return L > 0 ? (int)L : 0;
}
__device__ __forceinline__ int dev_lb(const int* a, int n, int v) {
    int lo = 0, hi = n;
    while (lo < hi) { int m = (lo+hi)>>1; if (a[m] < v) lo = m+1; else hi = m; }
    return lo;
}

// numpy FLOAT_pairwise_sum of squares of a[0..n) (stride 1), bit-exact
__device__ float np_psq(const float* a, int n) {
    if (n < 8) {
        float r = 0.f;
        for (int i = 0; i < n; i++) r = __fadd_rn(r, __fmul_rn(a[i], a[i]));
        return r;
    } else if (n <= 128) {
        float r[8];
        #pragma unroll
        for (int j = 0; j < 8; j++) r[j] = __fmul_rn(a[j], a[j]);
        int i = 8;
        for (; i < n - (n % 8); i += 8) {
            #pragma unroll
            for (int j = 0; j < 8; j++)
                r[j] = __fadd_rn(r[j], __fmul_rn(a[i+j], a[i+j]));
        }
        float res = __fadd_rn(__fadd_rn(__fadd_rn(r[0],r[1]), __fadd_rn(r[2],r[3])),
                              __fadd_rn(__fadd_rn(r[4],r[5]), __fadd_rn(r[6],r[7])));
        for (; i < n; i++) res = __fadd_rn(res, __fmul_rn(a[i], a[i]));
        return res;
    } else {
        int n2 = n / 2; n2 -= n2 % 8;
        return __fadd_rn(np_psq(a, n2), np_psq(a + n2, n - n2));
    }
}

__global__ void K_init() {
    int t = threadIdx.x;
    if (t == 0) {
        g_absbits = 0u; g_anygate = 0; g_minbits = 0xFFFFFFFFu; g_median = 0.f;
        g_cs0 = g_ce0 = g_cs1 = g_ce1 = 0; g_nruns0 = g_nruns1 = 0;
        g_tail = 0; g_copy = 0; g_ncand = 0; g_npk = 0; g_nops = 0;
    }
    for (int i = t; i < NWALK; i += blockDim.x) g_wcnt[i] = 0;
    for (int i = t; i < MAXRUNS; i += blockDim.x) g_lastApp[i] = INT_MIN;
}

__global__ void K_zero(float* out, int T) {
    int t = blockIdx.x*blockDim.x + threadIdx.x;
    if (t < T) out[t] = 0.f;
}

__global__ void K_absmax(const float* __restrict__ x, int T) {
    float m = 0.f;
    for (int i = blockIdx.x*blockDim.x + threadIdx.x; i < T; i += gridDim.x*blockDim.x)
        m = fmaxf(m, fabsf(x[i]));
    for (int o = 16; o; o >>= 1) m = fmaxf(m, __shfl_down_sync(0xFFFFFFFFu, m, o));
    if ((threadIdx.x & 31) == 0) atomicMax(&g_absbits, __float_as_uint(m));
}

__global__ void K_median(const float* __restrict__ p, int S, const int* __restrict__ stepsPtr) {
    __shared__ int sh_np, sh_any;
    int tid = threadIdx.x;
    if (tid == 0) { sh_np = 0; sh_any = 0; }
    __syncthreads();
    int cnp = 0, cany = 0;
    for (int j = tid; j < S; j += blockDim.x) {
        float v = p[j];
        if (v > 0.f) cnp++;
        if (v > 1e-5f) cany = 1;
    }
    atomicAdd(&sh_np, cnp);
    if (cany) atomicOr(&sh_any, 1);
    __syncthreads();
    int npos = sh_np;
    if (tid == 0) {
        g_anygate = sh_any;
        double fac = pow(2.0, (double)stepsPtr[0] / 12.0);
        g_factor32 = (float)fac;
    }
    if (npos > 0) {
        int kk = (npos - 1) >> 1;
        for (int j = tid; j < S; j += blockDim.x) {
            float v = p[j];
            if (v > 0.f) {
                int cl = 0, ce = 0;
                for (int t2 = 0; t2 < S; t2++) {
                    float u = p[t2];
                    if (u > 0.f) { cl += (u < v); ce += (u == v); }
                }
                if (cl <= kk && kk < cl + ce) g_median = v;
            }
        }
    }
    __syncthreads();
    if (tid == 0) {
        double fac = pow(2.0, (double)stepsPtr[0] / 12.0);
        g_mshift32 = (float)((double)g_median * fac);
    }
}

__global__ void K_interp(const float* __restrict__ p, int S, int T) {
    int t = blockIdx.x*blockDim.x + threadIdx.x;
    if (t >= T) return;
    double scale = (double)S / (double)T;
    double x = __dadd_rn(__dmul_rn(__dadd_rn((double)t, 0.5), scale), -0.5);
    if (x < 0.0) x = 0.0;
    double hi = (double)(S - 1);
    if (x > hi) x = hi;
    long i0 = (long)floor(x);
    long i1 = i0 + 1; if (i1 > (long)(S-1)) i1 = S - 1;
    float f = (float)__dsub_rn(x, (double)i0);
    g_f0[t] = __fadd_rn(__fmul_rn(p[i0], __fsub_rn(1.0f, f)), __fmul_rn(p[i1], f));
}

__global__ void K_shift(const float* __restrict__ prp, int T) {
    int t = blockIdx.x*blockDim.x + threadIdx.x;
    float res = 0.f;
    if (t < T) {
        float fs = __fmul_rn(g_f0[t], g_factor32);
        float m = g_mshift32;
        if (fs > 0.f) res = __fadd_rn(m, __fmul_rn(__fsub_rn(fs, m), prp[0]));
        g_f0s[t] = res;
    }
    unsigned mb = (t < T && res > 0.f) ? __float_as_uint(res) : 0xFFFFFFFFu;
    for (int o = 16; o; o >>= 1) mb = min(mb, __shfl_down_sync(0xFFFFFFFFu, mb, o));
    if ((threadIdx.x & 31) == 0 && mb != 0xFFFFFFFFu) atomicMin(&g_minbits, mb);
}

__global__ void K_mark(int T) {
    int t = blockIdx.x*blockDim.x + threadIdx.x;
    if (t >= T) return;
    if (g_f0[t] > 0.f) {
        bool pr = (t > 0) && (g_f0[t-1] > 0.f);
        bool nx = (t < T-1) && (g_f0[t+1] > 0.f);
        if (!pr) { int i = atomicAdd(&g_cs0,1); if (i < MAXRUNS) g_st0[i] = t; }
        if (!nx) { int i = atomicAdd(&g_ce0,1); if (i < MAXRUNS) g_en0[i] = t+1; }
    }
    if (g_f0s[t] > 0.f) {
        bool pr = (t > 0) && (g_f0s[t-1] > 0.f);
        bool nx = (t < T-1) && (g_f0s[t+1] > 0.f);
        if (!pr) { int i = atomicAdd(&g_cs1,1); if (i < MAXRUNS) g_st1[i] = t; }
        if (!nx) { int i = atomicAdd(&g_ce1,1); if (i < MAXRUNS) g_en1[i] = t+1; }
    }
}

__device__ void sort_small(int* a, int n) {
    for (int i = 1; i < n; i++) {
        int v = a[i], j = i-1;
        while (j >= 0 && a[j] > v) { a[j+1] = a[j]; j--; }
        a[j+1] = v;
    }
}

__global__ void K_sortruns() {
    if (threadIdx.x || blockIdx.x) return;
    {
        int ns = min(g_cs0, MAXRUNS), ne = min(g_ce0, MAXRUNS);
        sort_small(g_st0, ns); sort_small(g_en0, ne);
        int n = min(ns, ne), off = 0;
        if (n > 0 && g_st0[0] == 0) { g_st0[0] = 1; if (g_st0[0] >= g_en0[0]) off = 1; }
        int m = 0;
        for (int k = off; k < n; k++) { g_runL0[m] = g_st0[k]; g_runR0[m] = g_en0[k]; m++; }
        g_nruns0 = m;
    }
    {
        int ns = min(g_cs1, MAXRUNS), ne = min(g_ce1, MAXRUNS);
        sort_small(g_st1, ns); sort_small(g_en1, ne);
        int n = min(ns, ne), off = 0;
        if (n > 0 && g_st1[0] == 0) { g_st1[0] = 1; if (g_st1[0] >= g_en1[0]) off = 1; }
        int m = 0;
        for (int k = off; k < n; k++) { g_runL1[m] = g_st1[k]; g_runR1[m] = g_en1[k]; m++; }
        g_nruns1 = m;
    }
}

__global__ void K_backup(const float* __restrict__ sig, int T) {
    int run = blockIdx.x;
    if (run >= g_nruns0 || threadIdx.x != 0) return;
    int left = g_runL0[run], right = g_runR0[run];
    int middle = (left + right) / 2;
    double wd = __ddiv_rn(22050.0, (double)g_f0[middle]);
    long w = (wd > 2.0e9) ? 2000000000L : (long)wd;
    long s = (long)middle - w/2; if (s < 0) s = 0;
    long len = w; if (s + len > T) len = T - s;
    float mn = INFINITY, mx = -INFINITY; long imn = 0, imx = 0;
    for (long k = 0; k < len; k++) {
        float v = sig[s+k];
        if (v < mn) { mn = v; imn = k; }
        if (v > mx) { mx = v; imx = k; }
    }
    g_backup[run] = (mn == mx) ? middle
                  : (int)(s + ((fabs((double)mn) > fabs((double)mx)) ? imn : imx));
}

// one block per run; dir=1 right walk, dir=0 left walk (after K_scanAR)
__global__ __launch_bounds__(256) void K_walk(const float* __restrict__ sig, int T, int dir) {
    __shared__ int sw, ss_, scl, snc, svalid, sstop;
    __shared__ float s_q[MAXC];
    __shared__ float s_ma[MAXC];
    __shared__ float s_b[MAXW];     // normalized reference (f32, numpy-exact)
    __shared__ float s_nb;
    int run = blockIdx.x;
    if (run >= g_nruns0) return;
    int tid = threadIdx.x;
    int left = g_runL0[run], right = g_runR0[run];
    double gp = (double)__uint_as_float(g_absbits);
    long base = (long)(dir ? run : MAXRUNS + run) * CANDW;
    int i = 0, cnt = 0, lastApp = INT_MIN;
    double AR = -1e308;
    if (tid == 0) {
        i = g_backup[run];
        if (!dir) AR = g_AR[run];
    }
    for (int it = 0; it < 8192; it++) {
        if (tid == 0) {
            double f0i = (double)g_f0[i];
            double fm = f0i > 60.0 ? f0i : 60.0;
            int w = (int)__ddiv_rn(22050.0, fm);
            int s = i - w/2; if (s < 0) s = 0;
            int cl, cr;
            if (dir) {
                cl = (int)__dadd_rn((double)i, __dmul_rn(0.3,  (double)w));
                cr = (int)__dadd_rn((double)i, __dmul_rn(0.75, (double)w));
            } else {
                int a1 = (int)__dsub_rn((double)i, __dmul_rn(1.75, (double)w)); cl = a1 > 0 ? a1 : 0;
                int a2 = (int)__dsub_rn((double)i, __dmul_rn(1.3,  (double)w)); cr = a2 > 0 ? a2 : 0;
            }
            int valid = 0, nc = 0;
            if (!(cl == cr || (T - cl) < w)) {
                long hi = (long)cr + w; if (hi > T) hi = T;
                nc = (int)(hi - cl - w + 1);
                valid = (nc >= 1 && nc <= MAXC && w <= MAXW && s + w <= T);
            }
            sw = w; ss_ = s; scl = cl; snc = nc; svalid = valid; sstop = 0;
            if (valid) {
                float nb = __fsqrt_rn(np_psq(sig + s, w));
                s_nb = fmaxf(nb, 1e-12f);
            }
        }
        __syncthreads();
        int w = sw, s = ss_, cl = scl, nc = snc;
        if (svalid) {
            float nb = s_nb;
            for (int k = tid; k < w; k += 256) s_b[k] = __fdiv_rn(sig[s+k], nb);
            __syncthreads();
            if (tid < nc) {
                const float* ap = sig + cl + tid;
                // candidate norm: numpy-exact f32 pairwise of squares
                float na = __fsqrt_rn(np_psq(ap, w));
                na = fmaxf(na, 1e-12f);
                // dot: OpenBLAS gemv_t style — 4 FMA lanes, tree combine, scalar-FMA tail
                float a0 = 0.f, a1 = 0.f, a2 = 0.f, a3 = 0.f;
                int w4 = w & ~3;
                float ma = 0.f;
                for (int k = 0; k < w4; k += 4) {
                    float v0 = ap[k], v1 = ap[k+1], v2 = ap[k+2], v3 = ap[k+3];
                    ma = fmaxf(ma, fmaxf(fmaxf(fabsf(v0), fabsf(v1)), fmaxf(fabsf(v2), fabsf(v3))));
                    a0 = fmaf(__fdiv_rn(v0, na), s_b[k],   a0);
                    a1 = fmaf(__fdiv_rn(v1, na), s_b[k+1], a1);
                    a2 = fmaf(__fdiv_rn(v2, na), s_b[k+2], a2);
                    a3 = fmaf(__fdiv_rn(v3, na), s_b[k+3], a3);
                }
                float res = __fadd_rn(__fadd_rn(a0, a1), __fadd_rn(a2, a3));
                for (int k = w4; k < w; k++) {
                    float v = ap[k];
                    ma = fmaxf(ma, fabsf(v));
                    res = fmaf(__fdiv_rn(v, na), s_b[k], res);
                }
                s_q[tid] = res;
                s_ma[tid] = ma;
            }
        }
        __syncthreads();
        if (tid == 0) {
            double corr = -1.0, peak = 0.0;
            if (svalid) {
                int r = 0; float bv = s_q[0];
                for (int c = 1; c < nc; c++) if (s_q[c] > bv) { bv = s_q[c]; r = c; }
                corr = (double)bv;
                peak = (double)s_ma[r];
                i = i + (r + cl) - s;
            }
            bool neg1 = (corr == -1.0);
            if (dir) {
                if (neg1) i += w;
                if (i >= right) {
                    if (corr > 0.7 && peak > __dmul_rn(0.023333, gp)) {
                        if (cnt < CANDW) g_wci[base+cnt] = i;
                        cnt++; lastApp = i;
                    }
                    sstop = 1;
                } else if (corr > 0.3 && (peak == 0.0 || peak > __dmul_rn(0.01, gp))) {
                    if (cnt < CANDW) g_wci[base+cnt] = i;
                    cnt++; lastApp = i;
                }
            } else {
                if (neg1) i -= w;
                if (i < left) {
                    if (corr > 0.7 && peak > __dmul_rn(0.023333, gp) &&
                        __dsub_rn((double)i, AR) > __dmul_rn(0.8, (double)w)) {
                        if (cnt < CANDW) g_wci[base+cnt] = i;
                        cnt++;
                    }
                    sstop = 1;
                } else if (corr > 0.3 && (peak == 0.0 || peak > __dmul_rn(0.01, gp))) {
                    if (__dsub_rn((double)i, AR) > __dmul_rn(0.8, (double)w)) {
                        if (cnt < CANDW) g_wci[base+cnt] = i;
                        cnt++;
                    }
                }
            }
        }
        __syncthreads();
        if (sstop) break;
    }
    if (tid == 0) {
        g_wcnt[dir ? run : MAXRUNS + run] = min(cnt, CANDW);
        if (dir) g_lastApp[run] = lastApp;
    }
}

__global__ void K_scanAR() {
    if (threadIdx.x || blockIdx.x) return;
    double cur = -1e308;
    for (int r = 0; r < g_nruns0; r++) {
        g_AR[r] = cur;
        if (g_lastApp[r] != INT_MIN) cur = (double)g_lastApp[r];
    }
}

__global__ void K_collect() {
    __shared__ int s_off[NWALK];
    int tid = threadIdx.x;
    if (tid == 0) {
        int acc = 0;
        for (int sl = 0; sl < NWALK; sl++) { s_off[sl] = acc; acc += g_wcnt[sl]; }
        g_ncand = min(acc, MAXPK);
    }
    __syncthreads();
    for (int sl = 0; sl < NWALK; sl++) {
        int c = g_wcnt[sl], o = s_off[sl];
        for (int j = tid; j < c; j += blockDim.x)
            if (o + j < MAXPK) g_cand[o+j] = g_wci[(long)sl*CANDW + j];
    }
}

__global__ void K_rank(int T) {
    int N = g_ncand;
    for (int j = blockIdx.x*blockDim.x + threadIdx.x; j < N; j += gridDim.x*blockDim.x) {
        int v = g_cand[j], rk = 0;
        for (int k = 0; k < N; k++) {
            int u = g_cand[k];
            rk += (u < v) || (u == v && k < j);
        }
        int cv = v; if (cv < 0) cv = 0; if (cv > T-1) cv = T-1;
        g_peaks[rk] = cv;
    }
    if (blockIdx.x == 0 && threadIdx.x == 0) g_npk = N;
}

__device__ int plan_run(int r, int T, double max_w, int write, int base) {
    int left_v = g_runL1[r], right_v = g_runR1[r];
    int prevR = (r == 0) ? 0 : g_runR1[r-1];
    int cnt = 0, npk = g_npk;
    if (prevR < left_v) {
        if (write && base+cnt < MAXOPS) {
            g_opd[base+cnt] = prevR; g_opsrc[base+cnt] = prevR;
            g_opl[base+cnt] = left_v - prevR; g_opn[base+cnt] = left_v - prevR;
        }
        cnt++;
    }
    while (left_v < right_v) {
        int q = dev_lb(g_peaks, npk, left_v), p;
        if (q == 0) p = 0;
        else if (q >= npk) p = dev_lb(g_peaks, npk, g_peaks[npk-1]);
        else {
            long d1 = (long)left_v - g_peaks[q-1], d2 = (long)g_peaks[q] - left_v;
            p = (d1 <= d2) ? dev_lb(g_peaks, npk, g_peaks[q-1]) : q;
        }
        double fv = (double)g_f0s[left_v];
        int period = (int)__ddiv_rn(22050.0, fv > 60.0 ? fv : 60.0);
        int left_w = period/2, right_w = period/2;
        if (p > 0) {
            long d = (long)g_peaks[p] - g_peaks[p-1];
            if ((double)d <= max_w) left_w = min((int)d, left_w);
        }
        if (p < npk-1) {
            long d = (long)g_peaks[p+1] - g_peaks[p];
            if ((double)d <= max_w) right_w = min((int)d, right_w);
        }
        int left_i = g_peaks[p] - left_w; if (left_i < 0) left_i = 0;
        int right_i = g_peaks[p] + right_w;
        int ival = (right_i - left_i) / 2;
        if (ival <= 0) break;
        long a = (long)left_v - ival;
        int seglen = min(pyslen(a, (long)left_v + ival, T),
                         pyslen(left_i, (long)left_i + 2L*ival, T));
        int Ld = pyslen(a, a + seglen, T);
        int Ls = pyslen(left_i, (long)left_i + seglen, T);
        int L = min(min(Ld, Ls), seglen);
        if (write && base+cnt < MAXOPS) {
            long as_ = a < 0 ? a + T : a;
            g_opd[base+cnt] = (int)as_; g_opsrc[base+cnt] = left_i;
            g_opl[base+cnt] = L; g_opn[base+cnt] = 2*ival;
        }
        cnt++;
        left_v += ival * 2;
    }
    return cnt;
}

__global__ void K_plan(int T) {
    __shared__ int s_cnt[MAXRUNS];
    __shared__ double s_maxw;
    int tid = threadIdx.x;
    if (tid == 0) {
        g_copy = (!g_anygate || g_npk == 0) ? 1 : 0;
        float mp = __uint_as_float(g_minbits);
        s_maxw = __ddiv_rn(27562.5, (double)mp);
        g_tail = 0; g_nops = 0;
    }
    __syncthreads();
    if (g_copy) return;
    int nr = g_nruns1;
    if (tid == 0 && nr > 0) g_tail = g_runR1[nr-1];
    if (tid < nr) s_cnt[tid] = plan_run(tid, T, s_maxw, 0, 0);
    __syncthreads();
    if (tid == 0) {
        int acc = 0;
        for (int r = 0; r < nr; r++) { int c = s_cnt[r]; s_cnt[r] = acc; acc += c; }
        g_nops = min(acc, MAXOPS);
    }
    __syncthreads();
    if (tid < nr) plan_run(tid, T, s_maxw, 1, s_cnt[tid]);
}

__global__ void K_apply(const float* __restrict__ snd, float* __restrict__ out, int T) {
    int b = blockIdx.x;
    if (b >= g_nops) return;
    int d0 = g_opd[b], s0 = g_opsrc[b], L = g_opl[b], n = g_opn[b];
    for (int k = threadIdx.x; k < L; k += blockDim.x) {
        double ang = __ddiv_rn(__dmul_rn(6.283185307179586, (double)k), (double)n);
        float wf = (float)__dsub_rn(0.5, __dmul_rn(0.5, cos(ang)));
        atomicAdd(out + d0 + k, __fmul_rn(wf, snd[s0 + k]));
    }
}

__global__ void K_tail(const float* __restrict__ snd, float* __restrict__ out, int T) {
    int t = blockIdx.x*blockDim.x + threadIdx.x;
    if (t >= T) return;
    if (g_copy || t >= g_tail) out[t] = snd[t];
}

extern "C" void kernel_launch(void* const* d_in, const int* in_sizes, int n_in,
                              void* d_out, int out_size) {
    const float* snd   = (const float*)d_in[0];
    const float* pitch = (const float*)d_in[1];
    const int*   steps = (const int*)d_in[2];
    const float* prng  = (const float*)d_in[3];
    float* out = (float*)d_out;
    int T = in_sizes[0];
    int S = in_sizes[1];

    K_init<<<1,256>>>();
    K_zero<<<GRID(T,256),256>>>(out, T);
    K_absmax<<<512,256>>>(snd, T);
    K_median<<<1,256>>>(pitch, S, steps);
    K_interp<<<GRID(T,256),256>>>(pitch, S, T);
    K_shift<<<GRID(T,256),256>>>(prng, T);
    K_mark<<<GRID(T,256),256>>>(T);
    K_sortruns<<<1,1>>>();
    K_backup<<<MAXRUNS,1>>>(snd, T);
    K_walk<<<MAXRUNS,256>>>(snd, T, 1);
    K_scanAR<<<1,1>>>();
    K_walk<<<MAXRUNS,256>>>(snd, T, 0);
    K_collect<<<1,256>>>();
    K_rank<<<64,256>>>(T);
    K_plan<<<1,64>>>(T);
    K_apply<<<MAXOPS,128>>>(snd, out, T);
    K_tail<<<GRID(T,256),256>>>(snd, out, T);
}

// round 6
// speedup vs baseline: 1.4259x; 1.4259x over previous
#include <cuda_runtime.h>
#include <math.h>
#include <limits.h>

#define MAXT 700000
#define MAXRUNS 64
#define NWALK (2*MAXRUNS)
#define CANDW 2048
#define MAXPK 16384
#define MAXOPS 8192
#define MAXC 256
#define MAXW 400
#define MS 4096
#define WT 512
#define GRID(n,b) (((n)+(b)-1)/(b))

__device__ float g_f0[MAXT];
__device__ float g_f0s[MAXT];
__device__ unsigned g_absbits;
__device__ int g_anygate;
__device__ unsigned g_minbits;
__device__ float g_median;
__device__ float g_factor32, g_mshift32;

__device__ int g_st0[MAXRUNS], g_en0[MAXRUNS], g_st1[MAXRUNS], g_en1[MAXRUNS];
__device__ int g_cs0, g_ce0, g_cs1, g_ce1;
__device__ int g_runL0[MAXRUNS], g_runR0[MAXRUNS], g_nruns0;
__device__ int g_runL1[MAXRUNS], g_runR1[MAXRUNS], g_nruns1;
__device__ int g_tail, g_copy;
__device__ int g_backup[MAXRUNS];

__device__ int g_wci[NWALK*CANDW];
__device__ int g_wcnt[NWALK];
__device__ int g_lastApp[MAXRUNS];
__device__ double g_AR[MAXRUNS];

__device__ int g_cand[MAXPK];
__device__ int g_ncand, g_npk;
__device__ int g_peaks[MAXPK];

__device__ int g_opd[MAXOPS], g_opsrc[MAXOPS], g_opl[MAXOPS], g_opn[MAXOPS];
__device__ int g_nops;

__device__ __forceinline__ int pyslen(long start, long stop, long n) {
    if (start < 0) start += n; if (start < 0) start = 0; if (start > n) start = n;
    if (stop  < 0) stop  += n; if (stop  < 0) stop  = 0; if (stop  > n) stop  = n;
    long L = stop - start; return L > 0 ? (int)L : 0;
}
__device__ __forceinline__ int dev_lb(const int* a, int n, int v) {
    int lo = 0, hi = n;
    while (lo < hi) { int m = (lo+hi)>>1; if (a[m] < v) lo = m+1; else hi = m; }
    return lo;
}

// numpy FLOAT_pairwise_sum of squares, 4-lane cooperative version.
// All 4 lanes of an aligned group call with identical (a, n); result valid on lane 0.
// Bit-identical to the serial 8-chain pairwise algorithm.
__device__ float np_psq4(const float* a, int n, int lane) {
    if (n < 8) {
        float r = 0.f;
        for (int i = 0; i < n; i++) r = __fadd_rn(r, __fmul_rn(a[i], a[i]));
        return r;                      // all lanes compute; lane0's used
    }
    if (n <= 128) {
        int nb = n - (n % 8);
        int c0 = 2*lane, c1 = 2*lane + 1;
        float ra = __fmul_rn(a[c0], a[c0]);
        float rb = __fmul_rn(a[c1], a[c1]);
        for (int i = 8; i < nb; i += 8) {
            ra = __fadd_rn(ra, __fmul_rn(a[i+c0], a[i+c0]));
            rb = __fadd_rn(rb, __fmul_rn(a[i+c1], a[i+c1]));
        }
        float u = __fadd_rn(ra, rb);                       // u_l = r_{2l}+r_{2l+1}
        float u1 = __shfl_down_sync(0xFFFFFFFFu, u, 1, 4);
        float t  = __fadd_rn(u, u1);                       // lane0: u0+u1, lane2: u2+u3
        float t2 = __shfl_down_sync(0xFFFFFFFFu, t, 2, 4);
        float res = __fadd_rn(t, t2);                      // lane0: (u0+u1)+(u2+u3)
        for (int i = nb; i < n; i++) res = __fadd_rn(res, __fmul_rn(a[i], a[i]));
        return res;
    }
    int n2 = n / 2; n2 -= n2 % 8;
    float L = np_psq4(a, n2, lane);
    float R = np_psq4(a + n2, n - n2, lane);
    return __fadd_rn(L, R);
}

__global__ void K_init() {
    int t = threadIdx.x;
    if (t == 0) {
        g_absbits = 0u; g_anygate = 0; g_minbits = 0xFFFFFFFFu; g_median = 0.f;
        g_cs0 = g_ce0 = g_cs1 = g_ce1 = 0; g_nruns0 = g_nruns1 = 0;
        g_tail = 0; g_copy = 0; g_ncand = 0; g_npk = 0; g_nops = 0;
    }
    for (int i = t; i < NWALK; i += blockDim.x) g_wcnt[i] = 0;
    for (int i = t; i < MAXRUNS; i += blockDim.x) g_lastApp[i] = INT_MIN;
}

__global__ void K_zero(float* out, int T) {
    int t = blockIdx.x*blockDim.x + threadIdx.x;
    if (t < T) out[t] = 0.f;
}

__global__ void K_absmax(const float* __restrict__ x, int T) {
    float m = 0.f;
    for (int i = blockIdx.x*blockDim.x + threadIdx.x; i < T; i += gridDim.x*blockDim.x)
        m = fmaxf(m, fabsf(x[i]));
    for (int o = 16; o; o >>= 1) m = fmaxf(m, __shfl_down_sync(0xFFFFFFFFu, m, o));
    if ((threadIdx.x & 31) == 0) atomicMax(&g_absbits, __float_as_uint(m));
}

// gate + median of positives via smem bitonic sort (sorted set is order-independent)
__global__ void K_median(const float* __restrict__ p, int S, const int* __restrict__ stepsPtr) {
    __shared__ float buf[MS];
    __shared__ int sh_np, sh_any;
    int tid = threadIdx.x;
    if (tid == 0) { sh_np = 0; sh_any = 0; }
    __syncthreads();
    int cany = 0;
    for (int j = tid; j < S && j < MS; j += WT) {
        float v = p[j];
        if (v > 0.f) { int idx = atomicAdd(&sh_np, 1); buf[idx] = v; }
        if (v > 1e-5f) cany = 1;
    }
    if (cany) atomicOr(&sh_any, 1);
    __syncthreads();
    int npos = sh_np;
    for (int i = npos + tid; i < MS; i += WT) buf[i] = INFINITY;
    __syncthreads();
    // bitonic sort MS elements
    for (int k = 2; k <= MS; k <<= 1) {
        for (int j = k >> 1; j > 0; j >>= 1) {
            for (int i = tid; i < MS; i += WT) {
                int ixj = i ^ j;
                if (ixj > i) {
                    float a = buf[i], b = buf[ixj];
                    bool up = ((i & k) == 0);
                    if ((a > b) == up) { buf[i] = b; buf[ixj] = a; }
                }
            }
            __syncthreads();
        }
    }
    if (tid == 0) {
        g_anygate = sh_any;
        double fac = pow(2.0, (double)stepsPtr[0] / 12.0);
        g_factor32 = (float)fac;
        if (npos > 0) g_median = buf[(npos - 1) >> 1];
        g_mshift32 = (float)((double)g_median * fac);
    }
}

__global__ void K_interp(const float* __restrict__ p, int S, int T) {
    int t = blockIdx.x*blockDim.x + threadIdx.x;
    if (t >= T) return;
    double scale = (double)S / (double)T;
    double x = __dadd_rn(__dmul_rn(__dadd_rn((double)t, 0.5), scale), -0.5);
    if (x < 0.0) x = 0.0;
    double hi = (double)(S - 1);
    if (x > hi) x = hi;
    long i0 = (long)floor(x);
    long i1 = i0 + 1; if (i1 > (long)(S-1)) i1 = S - 1;
    float f = (float)__dsub_rn(x, (double)i0);
    g_f0[t] = __fadd_rn(__fmul_rn(p[i0], __fsub_rn(1.0f, f)), __fmul_rn(p[i1], f));
}

__global__ void K_shift(const float* __restrict__ prp, int T) {
    int t = blockIdx.x*blockDim.x + threadIdx.x;
    float res = 0.f;
    if (t < T) {
        float fs = __fmul_rn(g_f0[t], g_factor32);
        float m = g_mshift32;
        if (fs > 0.f) res = __fadd_rn(m, __fmul_rn(__fsub_rn(fs, m), prp[0]));
        g_f0s[t] = res;
    }
    unsigned mb = (t < T && res > 0.f) ? __float_as_uint(res) : 0xFFFFFFFFu;
    for (int o = 16; o; o >>= 1) mb = min(mb, __shfl_down_sync(0xFFFFFFFFu, mb, o));
    if ((threadIdx.x & 31) == 0 && mb != 0xFFFFFFFFu) atomicMin(&g_minbits, mb);
}

__global__ void K_mark(int T) {
    int t = blockIdx.x*blockDim.x + threadIdx.x;
    if (t >= T) return;
    if (g_f0[t] > 0.f) {
        bool pr = (t > 0) && (g_f0[t-1] > 0.f);
        bool nx = (t < T-1) && (g_f0[t+1] > 0.f);
        if (!pr) { int i = atomicAdd(&g_cs0,1); if (i < MAXRUNS) g_st0[i] = t; }
        if (!nx) { int i = atomicAdd(&g_ce0,1); if (i < MAXRUNS) g_en0[i] = t+1; }
    }
    if (g_f0s[t] > 0.f) {
        bool pr = (t > 0) && (g_f0s[t-1] > 0.f);
        bool nx = (t < T-1) && (g_f0s[t+1] > 0.f);
        if (!pr) { int i = atomicAdd(&g_cs1,1); if (i < MAXRUNS) g_st1[i] = t; }
        if (!nx) { int i = atomicAdd(&g_ce1,1); if (i < MAXRUNS) g_en1[i] = t+1; }
    }
}

__device__ void sort_small(int* a, int n) {
    for (int i = 1; i < n; i++) {
        int v = a[i], j = i-1;
        while (j >= 0 && a[j] > v) { a[j+1] = a[j]; j--; }
        a[j+1] = v;
    }
}

__global__ void K_sortruns() {
    if (threadIdx.x || blockIdx.x) return;
    {
        int ns = min(g_cs0, MAXRUNS), ne = min(g_ce0, MAXRUNS);
        sort_small(g_st0, ns); sort_small(g_en0, ne);
        int n = min(ns, ne), off = 0;
        if (n > 0 && g_st0[0] == 0) { g_st0[0] = 1; if (g_st0[0] >= g_en0[0]) off = 1; }
        int m = 0;
        for (int k = off; k < n; k++) { g_runL0[m] = g_st0[k]; g_runR0[m] = g_en0[k]; m++; }
        g_nruns0 = m;
    }
    {
        int ns = min(g_cs1, MAXRUNS), ne = min(g_ce1, MAXRUNS);
        sort_small(g_st1, ns); sort_small(g_en1, ne);
        int n = min(ns, ne), off = 0;
        if (n > 0 && g_st1[0] == 0) { g_st1[0] = 1; if (g_st1[0] >= g_en1[0]) off = 1; }
        int m = 0;
        for (int k = off; k < n; k++) { g_runL1[m] = g_st1[k]; g_runR1[m] = g_en1[k]; m++; }
        g_nruns1 = m;
    }
}

__global__ void K_backup(const float* __restrict__ sig, int T) {
    int run = blockIdx.x;
    if (run >= g_nruns0 || threadIdx.x != 0) return;
    int left = g_runL0[run], right = g_runR0[run];
    int middle = (left + right) / 2;
    double wd = __ddiv_rn(22050.0, (double)g_f0[middle]);
    long w = (wd > 2.0e9) ? 2000000000L : (long)wd;
    long s = (long)middle - w/2; if (s < 0) s = 0;
    long len = w; if (s + len > T) len = T - s;
    float mn = INFINITY, mx = -INFINITY; long imn = 0, imx = 0;
    for (long k = 0; k < len; k++) {
        float v = sig[s+k];
        if (v < mn) { mn = v; imn = k; }
        if (v > mx) { mx = v; imx = k; }
    }
    g_backup[run] = (mn == mx) ? middle
                  : (int)(s + ((fabs((double)mn) > fabs((double)mx)) ? imn : imx));
}

// one block per run; dir=1 right walk, dir=0 left walk (after K_scanAR)
__global__ __launch_bounds__(WT) void K_walk(const float* __restrict__ sig, int T, int dir) {
    __shared__ int sw, ss_, scl, snc, svalid, sstop, sbestr;
    __shared__ float s_q[MAXC];
    __shared__ float s_ma[MAXC];
    __shared__ float s_b[MAXW];
    __shared__ float s_nb;
    __shared__ float s_pv[WT/32];
    __shared__ int   s_pi[WT/32];
    int run = blockIdx.x;
    if (run >= g_nruns0) return;
    int tid = threadIdx.x, lane4 = tid & 3, grp = tid >> 2, wrp = tid >> 5, wl = tid & 31;
    int left = g_runL0[run], right = g_runR0[run];
    double gp = (double)__uint_as_float(g_absbits);
    long base = (long)(dir ? run : MAXRUNS + run) * CANDW;
    int i = 0, cnt = 0, lastApp = INT_MIN;
    double AR = -1e308;
    if (tid == 0) {
        i = g_backup[run];
        if (!dir) AR = g_AR[run];
    }
    for (int it = 0; it < 8192; it++) {
        if (tid == 0) {
            double f0i = (double)g_f0[i];
            double fm = f0i > 60.0 ? f0i : 60.0;
            int w = (int)__ddiv_rn(22050.0, fm);
            int s = i - w/2; if (s < 0) s = 0;
            int cl, cr;
            if (dir) {
                cl = (int)__dadd_rn((double)i, __dmul_rn(0.3,  (double)w));
                cr = (int)__dadd_rn((double)i, __dmul_rn(0.75, (double)w));
            } else {
                int a1 = (int)__dsub_rn((double)i, __dmul_rn(1.75, (double)w)); cl = a1 > 0 ? a1 : 0;
                int a2 = (int)__dsub_rn((double)i, __dmul_rn(1.3,  (double)w)); cr = a2 > 0 ? a2 : 0;
            }
            int valid = 0, nc = 0;
            if (!(cl == cr || (T - cl) < w)) {
                long hi = (long)cr + w; if (hi > T) hi = T;
                nc = (int)(hi - cl - w + 1);
                valid = (nc >= 1 && nc <= MAXC && w <= MAXW && s + w <= T);
            }
            sw = w; ss_ = s; scl = cl; snc = nc; svalid = valid; sstop = 0;
        }
        __syncthreads();
        int w = sw, s = ss_, cl = scl, nc = snc;
        if (svalid) {
            // ref norm: warp 0, groups of 4 compute redundantly, lane0 writes
            if (wrp == 0) {
                float psq = np_psq4(sig + s, w, lane4);
                if (tid == 0) s_nb = fmaxf(__fsqrt_rn(psq), 1e-12f);
            }
            __syncthreads();
            float nb = s_nb;
            for (int k = tid; k < w; k += WT) s_b[k] = __fdiv_rn(sig[s+k], nb);
            __syncthreads();
            // candidates: 4 lanes per candidate
            int nrounds = (nc + (WT/4) - 1) / (WT/4);
            for (int rr = 0; rr < nrounds; rr++) {
                int c = rr * (WT/4) + grp;
                int cc = c < nc ? c : nc - 1;
                const float* ap = sig + cl + cc;
                float psq = np_psq4(ap, w, lane4);
                float na = 0.f;
                if (lane4 == 0) na = fmaxf(__fsqrt_rn(psq), 1e-12f);
                na = __shfl_sync(0xFFFFFFFFu, na, 0, 4);
                int w4 = w & ~3;
                float acc = 0.f, ma = 0.f;
                for (int k = lane4; k < w4; k += 4) {
                    float v = ap[k];
                    ma = fmaxf(ma, fabsf(v));
                    acc = fmaf(__fdiv_rn(v, na), s_b[k], acc);
                }
                float a1 = __shfl_down_sync(0xFFFFFFFFu, acc, 1, 4);
                float ssum = __fadd_rn(acc, a1);                   // lane0:a0+a1 lane2:a2+a3
                float a2 = __shfl_down_sync(0xFFFFFFFFu, ssum, 2, 4);
                float res = __fadd_rn(ssum, a2);                   // lane0
                float m1 = __shfl_down_sync(0xFFFFFFFFu, ma, 1, 4);
                ma = fmaxf(ma, m1);
                float m2 = __shfl_down_sync(0xFFFFFFFFu, ma, 2, 4);
                ma = fmaxf(ma, m2);
                if (lane4 == 0) {
                    for (int k = w4; k < w; k++) {
                        float v = ap[k];
                        ma = fmaxf(ma, fabsf(v));
                        res = fmaf(__fdiv_rn(v, na), s_b[k], res);
                    }
                    if (c < nc) { s_q[c] = res; s_ma[c] = ma; }
                }
            }
            __syncthreads();
            // parallel argmax, first-occurrence tie-break
            {
                int idx = tid;
                float v = (idx < nc) ? s_q[idx] : -INFINITY;
                for (int o = 16; o; o >>= 1) {
                    float vo = __shfl_down_sync(0xFFFFFFFFu, v, o);
                    int   io = __shfl_down_sync(0xFFFFFFFFu, idx, o);
                    if (vo > v || (vo == v && io < idx)) { v = vo; idx = io; }
                }
                if (wl == 0) { s_pv[wrp] = v; s_pi[wrp] = idx; }
            }
            __syncthreads();
            if (tid == 0) {
                float bv = s_pv[0]; int br = s_pi[0];
                for (int q = 1; q < WT/32; q++)
                    if (s_pv[q] > bv) { bv = s_pv[q]; br = s_pi[q]; }
                sbestr = br;
            }
            __syncthreads();
        }
        if (tid == 0) {
            double corr = -1.0, peak = 0.0;
            if (svalid) {
                int r = sbestr;
                corr = (double)s_q[r];
                peak = (double)s_ma[r];
                i = i + (r + cl) - s;
            }
            bool neg1 = (corr == -1.0);
            if (dir) {
                if (neg1) i += w;
                if (i >= right) {
                    if (corr > 0.7 && peak > __dmul_rn(0.023333, gp)) {
                        if (cnt < CANDW) g_wci[base+cnt] = i;
                        cnt++; lastApp = i;
                    }
                    sstop = 1;
                } else if (corr > 0.3 && (peak == 0.0 || peak > __dmul_rn(0.01, gp))) {
                    if (cnt < CANDW) g_wci[base+cnt] = i;
                    cnt++; lastApp = i;
                }
            } else {
                if (neg1) i -= w;
                if (i < left) {
                    if (corr > 0.7 && peak > __dmul_rn(0.023333, gp) &&
                        __dsub_rn((double)i, AR) > __dmul_rn(0.8, (double)w)) {
                        if (cnt < CANDW) g_wci[base+cnt] = i;
                        cnt++;
                    }
                    sstop = 1;
                } else if (corr > 0.3 && (peak == 0.0 || peak > __dmul_rn(0.01, gp))) {
                    if (__dsub_rn((double)i, AR) > __dmul_rn(0.8, (double)w)) {
                        if (cnt < CANDW) g_wci[base+cnt] = i;
                        cnt++;
                    }
                }
            }
        }
        __syncthreads();
        if (sstop) break;
    }
    if (tid == 0) {
        g_wcnt[dir ? run : MAXRUNS + run] = min(cnt, CANDW);
        if (dir) g_lastApp[run] = lastApp;
    }
}

__global__ void K_scanAR() {
    if (threadIdx.x || blockIdx.x) return;
    double cur = -1e308;
    for (int r = 0; r < g_nruns0; r++) {
        g_AR[r] = cur;
        if (g_lastApp[r] != INT_MIN) cur = (double)g_lastApp[r];
    }
}

__global__ void K_collect() {
    __shared__ int s_off[NWALK];
    int tid = threadIdx.x;
    if (tid == 0) {
        int acc = 0;
        for (int sl = 0; sl < NWALK; sl++) { s_off[sl] = acc; acc += g_wcnt[sl]; }
        g_ncand = min(acc, MAXPK);
    }
    __syncthreads();
    for (int sl = 0; sl < NWALK; sl++) {
        int c = g_wcnt[sl], o = s_off[sl];
        for (int j = tid; j < c; j += blockDim.x)
            if (o + j < MAXPK) g_cand[o+j] = g_wci[(long)sl*CANDW + j];
    }
}

__global__ void K_rank(int T) {
    int N = g_ncand;
    for (int j = blockIdx.x*blockDim.x + threadIdx.x; j < N; j += gridDim.x*blockDim.x) {
        int v = g_cand[j], rk = 0;
        for (int k = 0; k < N; k++) {
            int u = g_cand[k];
            rk += (u < v) || (u == v && k < j);
        }
        int cv = v; if (cv < 0) cv = 0; if (cv > T-1) cv = T-1;
        g_peaks[rk] = cv;
    }
    if (blockIdx.x == 0 && threadIdx.x == 0) g_npk = N;
}

__device__ int plan_run(int r, int T, double max_w, int write, int base) {
    int left_v = g_runL1[r], right_v = g_runR1[r];
    int prevR = (r == 0) ? 0 : g_runR1[r-1];
    int cnt = 0, npk = g_npk;
    if (prevR < left_v) {
        if (write && base+cnt < MAXOPS) {
            g_opd[base+cnt] = prevR; g_opsrc[base+cnt] = prevR;
            g_opl[base+cnt] = left_v - prevR; g_opn[base+cnt] = left_v - prevR;
        }
        cnt++;
    }
    while (left_v < right_v) {
        int q = dev_lb(g_peaks, npk, left_v), p;
        if (q == 0) p = 0;
        else if (q >= npk) p = dev_lb(g_peaks, npk, g_peaks[npk-1]);
        else {
            long d1 = (long)left_v - g_peaks[q-1], d2 = (long)g_peaks[q] - left_v;
            p = (d1 <= d2) ? dev_lb(g_peaks, npk, g_peaks[q-1]) : q;
        }
        double fv = (double)g_f0s[left_v];
        int period = (int)__ddiv_rn(22050.0, fv > 60.0 ? fv : 60.0);
        int left_w = period/2, right_w = period/2;
        if (p > 0) {
            long d = (long)g_peaks[p] - g_peaks[p-1];
            if ((double)d <= max_w) left_w = min((int)d, left_w);
        }
        if (p < npk-1) {
            long d = (long)g_peaks[p+1] - g_peaks[p];
            if ((double)d <= max_w) right_w = min((int)d, right_w);
        }
        int left_i = g_peaks[p] - left_w; if (left_i < 0) left_i = 0;
        int right_i = g_peaks[p] + right_w;
        int ival = (right_i - left_i) / 2;
        if (ival <= 0) break;
        long a = (long)left_v - ival;
        int seglen = min(pyslen(a, (long)left_v + ival, T),
                         pyslen(left_i, (long)left_i + 2L*ival, T));
        int Ld = pyslen(a, a + seglen, T);
        int Ls = pyslen(left_i, (long)left_i + seglen, T);
        int L = min(min(Ld, Ls), seglen);
        if (write && base+cnt < MAXOPS) {
            long as_ = a < 0 ? a + T : a;
            g_opd[base+cnt] = (int)as_; g_opsrc[base+cnt] = left_i;
            g_opl[base+cnt] = L; g_opn[base+cnt] = 2*ival;
        }
        cnt++;
        left_v += ival * 2;
    }
    return cnt;
}

__global__ void K_plan(int T) {
    __shared__ int s_cnt[MAXRUNS];
    __shared__ double s_maxw;
    int tid = threadIdx.x;
    if (tid == 0) {
        g_copy = (!g_anygate || g_npk == 0) ? 1 : 0;
        float mp = __uint_as_float(g_minbits);
        s_maxw = __ddiv_rn(27562.5, (double)mp);
        g_tail = 0; g_nops = 0;
    }
    __syncthreads();
    if (g_copy) return;
    int nr = g_nruns1;
    if (tid == 0 && nr > 0) g_tail = g_runR1[nr-1];
    if (tid < nr) s_cnt[tid] = plan_run(tid, T, s_maxw, 0, 0);
    __syncthreads();
    if (tid == 0) {
        int acc = 0;
        for (int r = 0; r < nr; r++) { int c = s_cnt[r]; s_cnt[r] = acc; acc += c; }
        g_nops = min(acc, MAXOPS);
    }
    __syncthreads();
    if (tid < nr) plan_run(tid, T, s_maxw, 1, s_cnt[tid]);
}

__global__ void K_apply(const float* __restrict__ snd, float* __restrict__ out, int T) {
    int b = blockIdx.x;
    if (b >= g_nops) return;
    int d0 = g_opd[b], s0 = g_opsrc[b], L = g_opl[b], n = g_opn[b];
    for (int k = threadIdx.x; k < L; k += blockDim.x) {
        double ang = __ddiv_rn(__dmul_rn(6.283185307179586, (double)k), (double)n);
        float wf = (float)__dsub_rn(0.5, __dmul_rn(0.5, cos(ang)));
        atomicAdd(out + d0 + k, __fmul_rn(wf, snd[s0 + k]));
    }
}

__global__ void K_tail(const float* __restrict__ snd, float* __restrict__ out, int T) {
    int t = blockIdx.x*blockDim.x + threadIdx.x;
    if (t >= T) return;
    if (g_copy || t >= g_tail) out[t] = snd[t];
}

extern "C" void kernel_launch(void* const* d_in, const int* in_sizes, int n_in,
                              void* d_out, int out_size) {
    const float* snd   = (const float*)d_in[0];
    const float* pitch = (const float*)d_in[1];
    const int*   steps = (const int*)d_in[2];
    const float* prng  = (const float*)d_in[3];
    float* out = (float*)d_out;
    int T = in_sizes[0];
    int S = in_sizes[1];

    K_init<<<1,256>>>();
    K_zero<<<GRID(T,256),256>>>(out, T);
    K_absmax<<<512,256>>>(snd, T);
    K_median<<<1,WT>>>(pitch, S, steps);
    K_interp<<<GRID(T,256),256>>>(pitch, S, T);
    K_shift<<<GRID(T,256),256>>>(prng, T);
    K_mark<<<GRID(T,256),256>>>(T);
    K_sortruns<<<1,1>>>();
    K_backup<<<MAXRUNS,1>>>(snd, T);
    K_walk<<<MAXRUNS,WT>>>(snd, T, 1);
    K_scanAR<<<1,1>>>();
    K_walk<<<MAXRUNS,WT>>>(snd, T, 0);
    K_collect<<<1,256>>>();
    K_rank<<<64,256>>>(T);
    K_plan<<<1,64>>>(T);
    K_apply<<<MAXOPS,128>>>(snd, out, T);
    K_tail<<<GRID(T,256),256>>>(snd, out, T);
}

// round 7
// speedup vs baseline: 1.6473x; 1.1553x over previous
#include <cuda_runtime.h>
#include <math.h>
#include <limits.h>

#define MAXT 700000
#define MAXRUNS 64
#define NWALK (2*MAXRUNS)
#define CANDW 2048
#define MAXPK 16384
#define MAXOPS 8192
#define MAXC 256
#define MAXW 400
#define MS 4096
#define WIN 960
#define WTW 128
#define GRID(n,b) (((n)+(b)-1)/(b))

__device__ float g_f0[MAXT];
__device__ float g_f0s[MAXT];
__device__ unsigned g_absbits;
__device__ int g_anygate;
__device__ unsigned g_minbits;
__device__ float g_median;
__device__ float g_factor32, g_mshift32;

__device__ int g_st0[MAXRUNS], g_en0[MAXRUNS], g_st1[MAXRUNS], g_en1[MAXRUNS];
__device__ int g_cs0, g_ce0, g_cs1, g_ce1;
__device__ int g_runL0[MAXRUNS], g_runR0[MAXRUNS], g_nruns0;
__device__ int g_runL1[MAXRUNS], g_runR1[MAXRUNS], g_nruns1;
__device__ int g_tail, g_copy;
__device__ int g_backup[MAXRUNS];

__device__ int g_wci[NWALK*CANDW];
__device__ int g_wcw[NWALK*CANDW];
__device__ int g_wcnt[NWALK];
__device__ int g_lastApp[MAXRUNS];

__device__ int g_cand[MAXPK];
__device__ int g_ncand, g_npk;
__device__ int g_peaks[MAXPK];

__device__ int g_opd[MAXOPS], g_opsrc[MAXOPS], g_opl[MAXOPS], g_opn[MAXOPS];
__device__ int g_nops;

__device__ __forceinline__ int pyslen(long start, long stop, long n) {
    if (start < 0) start += n; if (start < 0) start = 0; if (start > n) start = n;
    if (stop  < 0) stop  += n; if (stop  < 0) stop  = 0; if (stop  > n) stop  = n;
    long L = stop - start; return L > 0 ? (int)L : 0;
}
__device__ __forceinline__ int dev_lb(const int* a, int n, int v) {
    int lo = 0, hi = n;
    while (lo < hi) { int m = (lo+hi)>>1; if (a[m] < v) lo = m+1; else hi = m; }
    return lo;
}

// numpy FLOAT_pairwise_sum of squares, 4-lane cooperative, bit-exact.
// All 4 lanes of an aligned group call with identical (a, n); result valid on lane 0 of group.
__device__ float np_psq4(const float* a, int n, int lane) {
    if (n < 8) {
        float r = 0.f;
        for (int i = 0; i < n; i++) r = __fadd_rn(r, __fmul_rn(a[i], a[i]));
        return r;
    }
    if (n <= 128) {
        int nb = n - (n % 8);
        int c0 = 2*lane, c1 = 2*lane + 1;
        float ra = __fmul_rn(a[c0], a[c0]);
        float rb = __fmul_rn(a[c1], a[c1]);
        for (int i = 8; i < nb; i += 8) {
            ra = __fadd_rn(ra, __fmul_rn(a[i+c0], a[i+c0]));
            rb = __fadd_rn(rb, __fmul_rn(a[i+c1], a[i+c1]));
        }
        float u = __fadd_rn(ra, rb);
        float u1 = __shfl_down_sync(0xFFFFFFFFu, u, 1, 4);
        float t  = __fadd_rn(u, u1);
        float t2 = __shfl_down_sync(0xFFFFFFFFu, t, 2, 4);
        float res = __fadd_rn(t, t2);
        for (int i = nb; i < n; i++) res = __fadd_rn(res, __fmul_rn(a[i], a[i]));
        return res;
    }
    int n2 = n / 2; n2 -= n2 % 8;
    float L = np_psq4(a, n2, lane);
    float R = np_psq4(a + n2, n - n2, lane);
    return __fadd_rn(L, R);
}

__global__ void K_init() {
    int t = threadIdx.x;
    if (t == 0) {
        g_absbits = 0u; g_anygate = 0; g_minbits = 0xFFFFFFFFu; g_median = 0.f;
        g_cs0 = g_ce0 = g_cs1 = g_ce1 = 0; g_nruns0 = g_nruns1 = 0;
        g_tail = 0; g_copy = 0; g_ncand = 0; g_npk = 0; g_nops = 0;
    }
    for (int i = t; i < NWALK; i += blockDim.x) g_wcnt[i] = 0;
    for (int i = t; i < MAXRUNS; i += blockDim.x) g_lastApp[i] = INT_MIN;
}

__global__ void K_zero(float* out, int T) {
    int t = blockIdx.x*blockDim.x + threadIdx.x;
    if (t < T) out[t] = 0.f;
}

__global__ void K_absmax(const float* __restrict__ x, int T) {
    float m = 0.f;
    for (int i = blockIdx.x*blockDim.x + threadIdx.x; i < T; i += gridDim.x*blockDim.x)
        m = fmaxf(m, fabsf(x[i]));
    for (int o = 16; o; o >>= 1) m = fmaxf(m, __shfl_down_sync(0xFFFFFFFFu, m, o));
    if ((threadIdx.x & 31) == 0) atomicMax(&g_absbits, __float_as_uint(m));
}

__global__ void K_median(const float* __restrict__ p, int S, const int* __restrict__ stepsPtr) {
    __shared__ float buf[MS];
    __shared__ int sh_np, sh_any;
    int tid = threadIdx.x;
    if (tid == 0) { sh_np = 0; sh_any = 0; }
    __syncthreads();
    int cany = 0;
    for (int j = tid; j < S && j < MS; j += 512) {
        float v = p[j];
        if (v > 0.f) { int idx = atomicAdd(&sh_np, 1); buf[idx] = v; }
        if (v > 1e-5f) cany = 1;
    }
    if (cany) atomicOr(&sh_any, 1);
    __syncthreads();
    int npos = sh_np;
    for (int i = npos + tid; i < MS; i += 512) buf[i] = INFINITY;
    __syncthreads();
    for (int k = 2; k <= MS; k <<= 1) {
        for (int j = k >> 1; j > 0; j >>= 1) {
            for (int i = tid; i < MS; i += 512) {
                int ixj = i ^ j;
                if (ixj > i) {
                    float a = buf[i], b = buf[ixj];
                    bool up = ((i & k) == 0);
                    if ((a > b) == up) { buf[i] = b; buf[ixj] = a; }
                }
            }
            __syncthreads();
        }
    }
    if (tid == 0) {
        g_anygate = sh_any;
        double fac = pow(2.0, (double)stepsPtr[0] / 12.0);
        g_factor32 = (float)fac;
        if (npos > 0) g_median = buf[(npos - 1) >> 1];
        g_mshift32 = (float)((double)g_median * fac);
    }
}

__global__ void K_interp(const float* __restrict__ p, int S, int T) {
    int t = blockIdx.x*blockDim.x + threadIdx.x;
    if (t >= T) return;
    double scale = (double)S / (double)T;
    double x = __dadd_rn(__dmul_rn(__dadd_rn((double)t, 0.5), scale), -0.5);
    if (x < 0.0) x = 0.0;
    double hi = (double)(S - 1);
    if (x > hi) x = hi;
    long i0 = (long)floor(x);
    long i1 = i0 + 1; if (i1 > (long)(S-1)) i1 = S - 1;
    float f = (float)__dsub_rn(x, (double)i0);
    g_f0[t] = __fadd_rn(__fmul_rn(p[i0], __fsub_rn(1.0f, f)), __fmul_rn(p[i1], f));
}

__global__ void K_shift(const float* __restrict__ prp, int T) {
    int t = blockIdx.x*blockDim.x + threadIdx.x;
    float res = 0.f;
    if (t < T) {
        float fs = __fmul_rn(g_f0[t], g_factor32);
        float m = g_mshift32;
        if (fs > 0.f) res = __fadd_rn(m, __fmul_rn(__fsub_rn(fs, m), prp[0]));
        g_f0s[t] = res;
    }
    unsigned mb = (t < T && res > 0.f) ? __float_as_uint(res) : 0xFFFFFFFFu;
    for (int o = 16; o; o >>= 1) mb = min(mb, __shfl_down_sync(0xFFFFFFFFu, mb, o));
    if ((threadIdx.x & 31) == 0 && mb != 0xFFFFFFFFu) atomicMin(&g_minbits, mb);
}

__global__ void K_mark(int T) {
    int t = blockIdx.x*blockDim.x + threadIdx.x;
    if (t >= T) return;
    if (g_f0[t] > 0.f) {
        bool pr = (t > 0) && (g_f0[t-1] > 0.f);
        bool nx = (t < T-1) && (g_f0[t+1] > 0.f);
        if (!pr) { int i = atomicAdd(&g_cs0,1); if (i < MAXRUNS) g_st0[i] = t; }
        if (!nx) { int i = atomicAdd(&g_ce0,1); if (i < MAXRUNS) g_en0[i] = t+1; }
    }
    if (g_f0s[t] > 0.f) {
        bool pr = (t > 0) && (g_f0s[t-1] > 0.f);
        bool nx = (t < T-1) && (g_f0s[t+1] > 0.f);
        if (!pr) { int i = atomicAdd(&g_cs1,1); if (i < MAXRUNS) g_st1[i] = t; }
        if (!nx) { int i = atomicAdd(&g_ce1,1); if (i < MAXRUNS) g_en1[i] = t+1; }
    }
}

__device__ void sort_small(int* a, int n) {
    for (int i = 1; i < n; i++) {
        int v = a[i], j = i-1;
        while (j >= 0 && a[j] > v) { a[j+1] = a[j]; j--; }
        a[j+1] = v;
    }
}

__global__ void K_sortruns() {
    if (threadIdx.x || blockIdx.x) return;
    {
        int ns = min(g_cs0, MAXRUNS), ne = min(g_ce0, MAXRUNS);
        sort_small(g_st0, ns); sort_small(g_en0, ne);
        int n = min(ns, ne), off = 0;
        if (n > 0 && g_st0[0] == 0) { g_st0[0] = 1; if (g_st0[0] >= g_en0[0]) off = 1; }
        int m = 0;
        for (int k = off; k < n; k++) { g_runL0[m] = g_st0[k]; g_runR0[m] = g_en0[k]; m++; }
        g_nruns0 = m;
    }
    {
        int ns = min(g_cs1, MAXRUNS), ne = min(g_ce1, MAXRUNS);
        sort_small(g_st1, ns); sort_small(g_en1, ne);
        int n = min(ns, ne), off = 0;
        if (n > 0 && g_st1[0] == 0) { g_st1[0] = 1; if (g_st1[0] >= g_en1[0]) off = 1; }
        int m = 0;
        for (int k = off; k < n; k++) { g_runL1[m] = g_st1[k]; g_runR1[m] = g_en1[k]; m++; }
        g_nruns1 = m;
    }
}

__global__ void K_backup(const float* __restrict__ sig, int T) {
    int run = blockIdx.x;
    if (run >= g_nruns0 || threadIdx.x != 0) return;
    int left = g_runL0[run], right = g_runR0[run];
    int middle = (left + right) / 2;
    double wd = __ddiv_rn(22050.0, (double)g_f0[middle]);
    long w = (wd > 2.0e9) ? 2000000000L : (long)wd;
    long s = (long)middle - w/2; if (s < 0) s = 0;
    long len = w; if (s + len > T) len = T - s;
    float mn = INFINITY, mx = -INFINITY; long imn = 0, imx = 0;
    for (long k = 0; k < len; k++) {
        float v = sig[s+k];
        if (v < mn) { mn = v; imn = k; }
        if (v > mx) { mx = v; imx = k; }
    }
    g_backup[run] = (mn == mx) ? middle
                  : (int)(s + ((fabs((double)mn) > fabs((double)mx)) ? imn : imx));
}

// Merged walk: blocks [0,MAXRUNS) = right walks, [MAXRUNS,2*MAXRUNS) = left walks.
// Left walks store (i,w) unfiltered; AR filter applied in K_filter (AR affects only appends).
__global__ __launch_bounds__(WTW) void K_walk(const float* __restrict__ sig, int T) {
    __shared__ float win[WIN];
    __shared__ float s_b[MAXW];
    __shared__ float s_q[MAXC], s_ma[MAXC];
    __shared__ float s_pv[WTW/32];
    __shared__ int   s_pi[WTW/32];
    __shared__ int sI, sStop;
    int b = blockIdx.x;
    int dir = (b < MAXRUNS) ? 1 : 0;
    int run = dir ? b : (b - MAXRUNS);
    if (run >= g_nruns0) return;
    int tid = threadIdx.x, lane4 = tid & 3, grp = tid >> 2, wrp = tid >> 5, wl = tid & 31;
    int left = g_runL0[run], right = g_runR0[run];
    double gp = (double)__uint_as_float(g_absbits);
    long base = (long)b * CANDW;
    int cnt = 0, lastApp = INT_MIN;
    if (tid == 0) { sI = g_backup[run]; sStop = 0; }
    __syncthreads();
    while (true) {
        int i = sI;
        // geometry: uniform redundant computation (deterministic)
        double f0i = (double)g_f0[i];
        double fm = f0i > 60.0 ? f0i : 60.0;
        int w = (int)__ddiv_rn(22050.0, fm);
        int s = i - w/2; if (s < 0) s = 0;
        int cl, cr;
        if (dir) {
            cl = (int)__dadd_rn((double)i, __dmul_rn(0.3,  (double)w));
            cr = (int)__dadd_rn((double)i, __dmul_rn(0.75, (double)w));
        } else {
            int a1 = (int)__dsub_rn((double)i, __dmul_rn(1.75, (double)w)); cl = a1 > 0 ? a1 : 0;
            int a2 = (int)__dsub_rn((double)i, __dmul_rn(1.3,  (double)w)); cr = a2 > 0 ? a2 : 0;
        }
        int valid = 0, nc = 0, base0 = 0;
        if (!(cl == cr || (T - cl) < w)) {
            long hi = (long)cr + w; if (hi > T) hi = T;
            nc = (int)(hi - cl - w + 1);
            valid = (nc >= 1 && nc <= MAXC && w <= MAXW && s + w <= T);
        }
        if (valid) {
            base0 = min(s, cl);
            int e1 = s + w, e2 = cl + nc - 1 + w;
            int WL = (e1 > e2 ? e1 : e2) - base0;
            if (WL > WIN) valid = 0;
            else {
                for (int k = tid; k < WL; k += WTW) win[k] = sig[base0 + k];
                __syncthreads();
                // warp 0: ref norm + normalized ref into s_b
                if (wrp == 0) {
                    const float* rp = win + (s - base0);
                    float psq = np_psq4(rp, w, lane4);
                    float nb = __shfl_sync(0xFFFFFFFFu, psq, 0);
                    nb = fmaxf(__fsqrt_rn(nb), 1e-12f);
                    for (int k = wl; k < w; k += 32) s_b[k] = __fdiv_rn(rp[k], nb);
                }
                __syncthreads();
                // candidates: 4 lanes per candidate, 32 groups
                const float* cb = win + (cl - base0);
                for (int c0 = 0; c0 < nc; c0 += WTW/4) {
                    int c = c0 + grp;
                    int cc = c < nc ? c : nc - 1;
                    const float* ap = cb + cc;
                    float psq = np_psq4(ap, w, lane4);
                    float na = 0.f;
                    if (lane4 == 0) na = fmaxf(__fsqrt_rn(psq), 1e-12f);
                    na = __shfl_sync(0xFFFFFFFFu, na, 0, 4);
                    int w4 = w & ~3;
                    float acc = 0.f, ma = 0.f;
                    for (int k = lane4; k < w4; k += 4) {
                        float v = ap[k];
                        ma = fmaxf(ma, fabsf(v));
                        acc = fmaf(__fdiv_rn(v, na), s_b[k], acc);
                    }
                    float a1 = __shfl_down_sync(0xFFFFFFFFu, acc, 1, 4);
                    float ssum = __fadd_rn(acc, a1);
                    float a2 = __shfl_down_sync(0xFFFFFFFFu, ssum, 2, 4);
                    float res = __fadd_rn(ssum, a2);
                    float m1 = __shfl_down_sync(0xFFFFFFFFu, ma, 1, 4);
                    ma = fmaxf(ma, m1);
                    float m2 = __shfl_down_sync(0xFFFFFFFFu, ma, 2, 4);
                    ma = fmaxf(ma, m2);
                    if (lane4 == 0) {
                        for (int k = w4; k < w; k++) {
                            float v = ap[k];
                            ma = fmaxf(ma, fabsf(v));
                            res = fmaf(__fdiv_rn(v, na), s_b[k], res);
                        }
                        if (c < nc) { s_q[c] = res; s_ma[c] = ma; }
                    }
                }
                __syncthreads();
                // argmax, first-occurrence tie-break
                {
                    float v = (tid < nc) ? s_q[tid] : -INFINITY;
                    int idx = tid;
                    int j2 = tid + WTW;
                    if (j2 < nc) { float v2 = s_q[j2]; if (v2 > v) { v = v2; idx = j2; } }
                    for (int o = 16; o; o >>= 1) {
                        float vo = __shfl_down_sync(0xFFFFFFFFu, v, o);
                        int   io = __shfl_down_sync(0xFFFFFFFFu, idx, o);
                        if (vo > v || (vo == v && io < idx)) { v = vo; idx = io; }
                    }
                    if (wl == 0) { s_pv[wrp] = v; s_pi[wrp] = idx; }
                }
                __syncthreads();
            }
        }
        if (tid == 0) {
            double corr = -1.0, peak = 0.0;
            int stop = 0;
            if (valid) {
                float bv = s_pv[0]; int br = s_pi[0];
                for (int q = 1; q < WTW/32; q++)
                    if (s_pv[q] > bv || (s_pv[q] == bv && s_pi[q] < br)) { bv = s_pv[q]; br = s_pi[q]; }
                corr = (double)s_q[br];
                peak = (double)s_ma[br];
                i = i + (br + cl) - s;
            }
            bool neg1 = (corr == -1.0);
            if (dir) {
                if (neg1) i += w;
                if (i >= right) {
                    if (corr > 0.7 && peak > __dmul_rn(0.023333, gp)) {
                        if (cnt < CANDW) g_wci[base+cnt] = i;
                        cnt++; lastApp = i;
                    }
                    stop = 1;
                } else if (corr > 0.3 && (peak == 0.0 || peak > __dmul_rn(0.01, gp))) {
                    if (cnt < CANDW) g_wci[base+cnt] = i;
                    cnt++; lastApp = i;
                }
            } else {
                if (neg1) i -= w;
                if (i < left) {
                    if (corr > 0.7 && peak > __dmul_rn(0.023333, gp)) {
                        if (cnt < CANDW) { g_wci[base+cnt] = i; g_wcw[base+cnt] = w; }
                        cnt++;
                    }
                    stop = 1;
                } else if (corr > 0.3 && (peak == 0.0 || peak > __dmul_rn(0.01, gp))) {
                    if (cnt < CANDW) { g_wci[base+cnt] = i; g_wcw[base+cnt] = w; }
                    cnt++;
                }
            }
            sI = i; sStop = stop;
        }
        __syncthreads();
        if (sStop) break;
    }
    if (tid == 0) {
        g_wcnt[b] = min(cnt, CANDW);
        if (dir) g_lastApp[run] = lastApp;
    }
}

// AR prefix + filter left-walk candidates (exact: AR constant per left walk)
__global__ void K_filter() {
    __shared__ double sAR[MAXRUNS];
    int tid = threadIdx.x;
    int nr = g_nruns0;
    if (tid == 0) {
        double cur = -1e308;
        for (int r = 0; r < nr; r++) {
            sAR[r] = cur;
            if (g_lastApp[r] != INT_MIN) cur = (double)g_lastApp[r];
        }
    }
    __syncthreads();
    if (tid < nr) {
        long base = (long)(MAXRUNS + tid) * CANDW;
        int c = g_wcnt[MAXRUNS + tid], m = 0;
        double AR = sAR[tid];
        for (int j = 0; j < c; j++) {
            int i = g_wci[base + j], w = g_wcw[base + j];
            if (__dsub_rn((double)i, AR) > __dmul_rn(0.8, (double)w)) {
                g_wci[base + m] = i; m++;
            }
        }
        g_wcnt[MAXRUNS + tid] = m;
    }
}

__global__ void K_collect() {
    __shared__ int s_off[NWALK];
    int tid = threadIdx.x;
    if (tid == 0) {
        int acc = 0;
        for (int sl = 0; sl < NWALK; sl++) { s_off[sl] = acc; acc += g_wcnt[sl]; }
        g_ncand = min(acc, MAXPK);
    }
    __syncthreads();
    for (int sl = 0; sl < NWALK; sl++) {
        int c = g_wcnt[sl], o = s_off[sl];
        for (int j = tid; j < c; j += blockDim.x)
            if (o + j < MAXPK) g_cand[o+j] = g_wci[(long)sl*CANDW + j];
    }
}

__global__ void K_rank(int T) {
    int N = g_ncand;
    for (int j = blockIdx.x*blockDim.x + threadIdx.x; j < N; j += gridDim.x*blockDim.x) {
        int v = g_cand[j], rk = 0;
        for (int k = 0; k < N; k++) {
            int u = g_cand[k];
            rk += (u < v) || (u == v && k < j);
        }
        int cv = v; if (cv < 0) cv = 0; if (cv > T-1) cv = T-1;
        g_peaks[rk] = cv;
    }
    if (blockIdx.x == 0 && threadIdx.x == 0) g_npk = N;
}

__device__ int plan_run(int r, int T, double max_w, int write, int base) {
    int left_v = g_runL1[r], right_v = g_runR1[r];
    int prevR = (r == 0) ? 0 : g_runR1[r-1];
    int cnt = 0, npk = g_npk;
    if (prevR < left_v) {
        if (write && base+cnt < MAXOPS) {
            g_opd[base+cnt] = prevR; g_opsrc[base+cnt] = prevR;
            g_opl[base+cnt] = left_v - prevR; g_opn[base+cnt] = left_v - prevR;
        }
        cnt++;
    }
    while (left_v < right_v) {
        int q = dev_lb(g_peaks, npk, left_v), p;
        if (q == 0) p = 0;
        else if (q >= npk) p = dev_lb(g_peaks, npk, g_peaks[npk-1]);
        else {
            long d1 = (long)left_v - g_peaks[q-1], d2 = (long)g_peaks[q] - left_v;
            p = (d1 <= d2) ? dev_lb(g_peaks, npk, g_peaks[q-1]) : q;
        }
        double fv = (double)g_f0s[left_v];
        int period = (int)__ddiv_rn(22050.0, fv > 60.0 ? fv : 60.0);
        int left_w = period/2, right_w = period/2;
        if (p > 0) {
            long d = (long)g_peaks[p] - g_peaks[p-1];
            if ((double)d <= max_w) left_w = min((int)d, left_w);
        }
        if (p < npk-1) {
            long d = (long)g_peaks[p+1] - g_peaks[p];
            if ((double)d <= max_w) right_w = min((int)d, right_w);
        }
        int left_i = g_peaks[p] - left_w; if (left_i < 0) left_i = 0;
        int right_i = g_peaks[p] + right_w;
        int ival = (right_i - left_i) / 2;
        if (ival <= 0) break;
        long a = (long)left_v - ival;
        int seglen = min(pyslen(a, (long)left_v + ival, T),
                         pyslen(left_i, (long)left_i + 2L*ival, T));
        int Ld = pyslen(a, a + seglen, T);
        int Ls = pyslen(left_i, (long)left_i + seglen, T);
        int L = min(min(Ld, Ls), seglen);
        if (write && base+cnt < MAXOPS) {
            long as_ = a < 0 ? a + T : a;
            g_opd[base+cnt] = (int)as_; g_opsrc[base+cnt] = left_i;
            g_opl[base+cnt] = L; g_opn[base+cnt] = 2*ival;
        }
        cnt++;
        left_v += ival * 2;
    }
    return cnt;
}

__global__ void K_plan(int T) {
    __shared__ int s_cnt[MAXRUNS];
    __shared__ double s_maxw;
    int tid = threadIdx.x;
    if (tid == 0) {
        g_copy = (!g_anygate || g_npk == 0) ? 1 : 0;
        float mp = __uint_as_float(g_minbits);
        s_maxw = __ddiv_rn(27562.5, (double)mp);
        g_tail = 0; g_nops = 0;
    }
    __syncthreads();
    if (g_copy) return;
    int nr = g_nruns1;
    if (tid == 0 && nr > 0) g_tail = g_runR1[nr-1];
    if (tid < nr) s_cnt[tid] = plan_run(tid, T, s_maxw, 0, 0);
    __syncthreads();
    if (tid == 0) {
        int acc = 0;
        for (int r = 0; r < nr; r++) { int c = s_cnt[r]; s_cnt[r] = acc; acc += c; }
        g_nops = min(acc, MAXOPS);
    }
    __syncthreads();
    if (tid < nr) plan_run(tid, T, s_maxw, 1, s_cnt[tid]);
}

__global__ void K_apply(const float* __restrict__ snd, float* __restrict__ out, int T) {
    for (int b = blockIdx.x; b < g_nops; b += gridDim.x) {
        int d0 = g_opd[b], s0 = g_opsrc[b], L = g_opl[b], n = g_opn[b];
        for (int k = threadIdx.x; k < L; k += blockDim.x) {
            double ang = __ddiv_rn(__dmul_rn(6.283185307179586, (double)k), (double)n);
            float wf = (float)__dsub_rn(0.5, __dmul_rn(0.5, cos(ang)));
            atomicAdd(out + d0 + k, __fmul_rn(wf, snd[s0 + k]));
        }
    }
}

__global__ void K_tail(const float* __restrict__ snd, float* __restrict__ out, int T) {
    int t = blockIdx.x*blockDim.x + threadIdx.x;
    if (t >= T) return;
    if (g_copy || t >= g_tail) out[t] = snd[t];
}

extern "C" void kernel_launch(void* const* d_in, const int* in_sizes, int n_in,
                              void* d_out, int out_size) {
    const float* snd   = (const float*)d_in[0];
    const float* pitch = (const float*)d_in[1];
    const int*   steps = (const int*)d_in[2];
    const float* prng  = (const float*)d_in[3];
    float* out = (float*)d_out;
    int T = in_sizes[0];
    int S = in_sizes[1];

    K_init<<<1,256>>>();
    K_zero<<<GRID(T,256),256>>>(out, T);
    K_absmax<<<512,256>>>(snd, T);
    K_median<<<1,512>>>(pitch, S, steps);
    K_interp<<<GRID(T,256),256>>>(pitch, S, T);
    K_shift<<<GRID(T,256),256>>>(prng, T);
    K_mark<<<GRID(T,256),256>>>(T);
    K_sortruns<<<1,1>>>();
    K_backup<<<MAXRUNS,1>>>(snd, T);
    K_walk<<<NWALK,WTW>>>(snd, T);        // merged right+left walks
    K_filter<<<1,64>>>();
    K_collect<<<1,256>>>();
    K_rank<<<64,256>>>(T);
    K_plan<<<1,64>>>(T);
    K_apply<<<2048,128>>>(snd, out, T);
    K_tail<<<GRID(T,256),256>>>(snd, out, T);
}

// round 8
// speedup vs baseline: 1.8558x; 1.1265x over previous
#include <cuda_runtime.h>
#include <math.h>
#include <limits.h>

#define MAXT 700000
#define MAXRUNS 64
#define NWALK (2*MAXRUNS)
#define CANDW 2048
#define MAXPK 16384
#define MAXOPS 8192
#define MAXC 256
#define MAXW 400
#define MS 4096
#define WIN 960
#define WTW 512
#define GRID(n,b) (((n)+(b)-1)/(b))

__device__ float g_f0[MAXT];
__device__ float g_f0s[MAXT];
__device__ unsigned g_absbits;
__device__ int g_anygate;
__device__ unsigned g_minbits;
__device__ float g_median;
__device__ float g_factor32, g_mshift32;

__device__ int g_st0[MAXRUNS], g_en0[MAXRUNS], g_st1[MAXRUNS], g_en1[MAXRUNS];
__device__ int g_cs0, g_ce0, g_cs1, g_ce1;
__device__ int g_runL0[MAXRUNS], g_runR0[MAXRUNS], g_nruns0;
__device__ int g_runL1[MAXRUNS], g_runR1[MAXRUNS], g_nruns1;
__device__ int g_tail, g_copy;
__device__ int g_backup[MAXRUNS];

__device__ int g_wci[NWALK*CANDW];
__device__ int g_wcw[NWALK*CANDW];
__device__ int g_wcnt[NWALK];
__device__ int g_lastApp[MAXRUNS];

__device__ int g_cand[MAXPK];
__device__ int g_ncand, g_npk;
__device__ int g_peaks[MAXPK];

__device__ int g_opd[MAXOPS], g_opsrc[MAXOPS], g_opl[MAXOPS], g_opn[MAXOPS];
__device__ int g_nops;

__device__ __forceinline__ int pyslen(long start, long stop, long n) {
    if (start < 0) start += n; if (start < 0) start = 0; if (start > n) start = n;
    if (stop  < 0) stop  += n; if (stop  < 0) stop  = 0; if (stop  > n) stop  = n;
    long L = stop - start; return L > 0 ? (int)L : 0;
}
__device__ __forceinline__ int dev_lb(const int* a, int n, int v) {
    int lo = 0, hi = n;
    while (lo < hi) { int m = (lo+hi)>>1; if (a[m] < v) lo = m+1; else hi = m; }
    return lo;
}

// numpy FLOAT_pairwise_sum of squares, 4-lane cooperative, bit-exact.
__device__ float np_psq4(const float* a, int n, int lane) {
    if (n < 8) {
        float r = 0.f;
        for (int i = 0; i < n; i++) r = __fadd_rn(r, __fmul_rn(a[i], a[i]));
        return r;
    }
    if (n <= 128) {
        int nb = n - (n % 8);
        int c0 = 2*lane, c1 = 2*lane + 1;
        float ra = __fmul_rn(a[c0], a[c0]);
        float rb = __fmul_rn(a[c1], a[c1]);
        for (int i = 8; i < nb; i += 8) {
            ra = __fadd_rn(ra, __fmul_rn(a[i+c0], a[i+c0]));
            rb = __fadd_rn(rb, __fmul_rn(a[i+c1], a[i+c1]));
        }
        float u = __fadd_rn(ra, rb);
        float u1 = __shfl_down_sync(0xFFFFFFFFu, u, 1, 4);
        float t  = __fadd_rn(u, u1);
        float t2 = __shfl_down_sync(0xFFFFFFFFu, t, 2, 4);
        float res = __fadd_rn(t, t2);
        for (int i = nb; i < n; i++) res = __fadd_rn(res, __fmul_rn(a[i], a[i]));
        return res;
    }
    int n2 = n / 2; n2 -= n2 % 8;
    float L = np_psq4(a, n2, lane);
    float R = np_psq4(a + n2, n - n2, lane);
    return __fadd_rn(L, R);
}

__global__ void K_init() {
    int t = threadIdx.x;
    if (t == 0) {
        g_absbits = 0u; g_anygate = 0; g_minbits = 0xFFFFFFFFu; g_median = 0.f;
        g_cs0 = g_ce0 = g_cs1 = g_ce1 = 0; g_nruns0 = g_nruns1 = 0;
        g_tail = 0; g_copy = 0; g_ncand = 0; g_npk = 0; g_nops = 0;
    }
    for (int i = t; i < NWALK; i += blockDim.x) g_wcnt[i] = 0;
    for (int i = t; i < MAXRUNS; i += blockDim.x) g_lastApp[i] = INT_MIN;
}

__global__ void K_zero(float* out, int T) {
    int t = blockIdx.x*blockDim.x + threadIdx.x;
    if (t < T) out[t] = 0.f;
}

__global__ void K_absmax(const float* __restrict__ x, int T) {
    float m = 0.f;
    for (int i = blockIdx.x*blockDim.x + threadIdx.x; i < T; i += gridDim.x*blockDim.x)
        m = fmaxf(m, fabsf(x[i]));
    for (int o = 16; o; o >>= 1) m = fmaxf(m, __shfl_down_sync(0xFFFFFFFFu, m, o));
    if ((threadIdx.x & 31) == 0) atomicMax(&g_absbits, __float_as_uint(m));
}

__global__ void K_median(const float* __restrict__ p, int S, const int* __restrict__ stepsPtr) {
    __shared__ float buf[MS];
    __shared__ int sh_np, sh_any;
    int tid = threadIdx.x;
    if (tid == 0) { sh_np = 0; sh_any = 0; }
    __syncthreads();
    int cany = 0;
    for (int j = tid; j < S && j < MS; j += 512) {
        float v = p[j];
        if (v > 0.f) { int idx = atomicAdd(&sh_np, 1); buf[idx] = v; }
        if (v > 1e-5f) cany = 1;
    }
    if (cany) atomicOr(&sh_any, 1);
    __syncthreads();
    int npos = sh_np;
    for (int i = npos + tid; i < MS; i += 512) buf[i] = INFINITY;
    __syncthreads();
    for (int k = 2; k <= MS; k <<= 1) {
        for (int j = k >> 1; j > 0; j >>= 1) {
            for (int i = tid; i < MS; i += 512) {
                int ixj = i ^ j;
                if (ixj > i) {
                    float a = buf[i], b = buf[ixj];
                    bool up = ((i & k) == 0);
                    if ((a > b) == up) { buf[i] = b; buf[ixj] = a; }
                }
            }
            __syncthreads();
        }
    }
    if (tid == 0) {
        g_anygate = sh_any;
        double fac = pow(2.0, (double)stepsPtr[0] / 12.0);
        g_factor32 = (float)fac;
        if (npos > 0) g_median = buf[(npos - 1) >> 1];
        g_mshift32 = (float)((double)g_median * fac);
    }
}

__global__ void K_interp(const float* __restrict__ p, int S, int T) {
    int t = blockIdx.x*blockDim.x + threadIdx.x;
    if (t >= T) return;
    double scale = (double)S / (double)T;
    double x = __dadd_rn(__dmul_rn(__dadd_rn((double)t, 0.5), scale), -0.5);
    if (x < 0.0) x = 0.0;
    double hi = (double)(S - 1);
    if (x > hi) x = hi;
    long i0 = (long)floor(x);
    long i1 = i0 + 1; if (i1 > (long)(S-1)) i1 = S - 1;
    float f = (float)__dsub_rn(x, (double)i0);
    g_f0[t] = __fadd_rn(__fmul_rn(p[i0], __fsub_rn(1.0f, f)), __fmul_rn(p[i1], f));
}

__global__ void K_shift(const float* __restrict__ prp, int T) {
    int t = blockIdx.x*blockDim.x + threadIdx.x;
    float res = 0.f;
    if (t < T) {
        float fs = __fmul_rn(g_f0[t], g_factor32);
        float m = g_mshift32;
        if (fs > 0.f) res = __fadd_rn(m, __fmul_rn(__fsub_rn(fs, m), prp[0]));
        g_f0s[t] = res;
    }
    unsigned mb = (t < T && res > 0.f) ? __float_as_uint(res) : 0xFFFFFFFFu;
    for (int o = 16; o; o >>= 1) mb = min(mb, __shfl_down_sync(0xFFFFFFFFu, mb, o));
    if ((threadIdx.x & 31) == 0 && mb != 0xFFFFFFFFu) atomicMin(&g_minbits, mb);
}

__global__ void K_mark(int T) {
    int t = blockIdx.x*blockDim.x + threadIdx.x;
    if (t >= T) return;
    if (g_f0[t] > 0.f) {
        bool pr = (t > 0) && (g_f0[t-1] > 0.f);
        bool nx = (t < T-1) && (g_f0[t+1] > 0.f);
        if (!pr) { int i = atomicAdd(&g_cs0,1); if (i < MAXRUNS) g_st0[i] = t; }
        if (!nx) { int i = atomicAdd(&g_ce0,1); if (i < MAXRUNS) g_en0[i] = t+1; }
    }
    if (g_f0s[t] > 0.f) {
        bool pr = (t > 0) && (g_f0s[t-1] > 0.f);
        bool nx = (t < T-1) && (g_f0s[t+1] > 0.f);
        if (!pr) { int i = atomicAdd(&g_cs1,1); if (i < MAXRUNS) g_st1[i] = t; }
        if (!nx) { int i = atomicAdd(&g_ce1,1); if (i < MAXRUNS) g_en1[i] = t+1; }
    }
}

__device__ void sort_small(int* a, int n) {
    for (int i = 1; i < n; i++) {
        int v = a[i], j = i-1;
        while (j >= 0 && a[j] > v) { a[j+1] = a[j]; j--; }
        a[j+1] = v;
    }
}

__global__ void K_sortruns() {
    if (threadIdx.x || blockIdx.x) return;
    {
        int ns = min(g_cs0, MAXRUNS), ne = min(g_ce0, MAXRUNS);
        sort_small(g_st0, ns); sort_small(g_en0, ne);
        int n = min(ns, ne), off = 0;
        if (n > 0 && g_st0[0] == 0) { g_st0[0] = 1; if (g_st0[0] >= g_en0[0]) off = 1; }
        int m = 0;
        for (int k = off; k < n; k++) { g_runL0[m] = g_st0[k]; g_runR0[m] = g_en0[k]; m++; }
        g_nruns0 = m;
    }
    {
        int ns = min(g_cs1, MAXRUNS), ne = min(g_ce1, MAXRUNS);
        sort_small(g_st1, ns); sort_small(g_en1, ne);
        int n = min(ns, ne), off = 0;
        if (n > 0 && g_st1[0] == 0) { g_st1[0] = 1; if (g_st1[0] >= g_en1[0]) off = 1; }
        int m = 0;
        for (int k = off; k < n; k++) { g_runL1[m] = g_st1[k]; g_runR1[m] = g_en1[k]; m++; }
        g_nruns1 = m;
    }
}

__global__ void K_backup(const float* __restrict__ sig, int T) {
    int run = blockIdx.x;
    if (run >= g_nruns0 || threadIdx.x != 0) return;
    int left = g_runL0[run], right = g_runR0[run];
    int middle = (left + right) / 2;
    double wd = __ddiv_rn(22050.0, (double)g_f0[middle]);
    long w = (wd > 2.0e9) ? 2000000000L : (long)wd;
    long s = (long)middle - w/2; if (s < 0) s = 0;
    long len = w; if (s + len > T) len = T - s;
    float mn = INFINITY, mx = -INFINITY; long imn = 0, imx = 0;
    for (long k = 0; k < len; k++) {
        float v = sig[s+k];
        if (v < mn) { mn = v; imn = k; }
        if (v > mx) { mx = v; imx = k; }
    }
    g_backup[run] = (mn == mx) ? middle
                  : (int)(s + ((fabs((double)mn) > fabs((double)mx)) ? imn : imx));
}

// Merged walk: blocks [0,MAXRUNS)=right, [MAXRUNS,NWALK)=left (AR filter post-hoc).
__global__ __launch_bounds__(WTW) void K_walk(const float* __restrict__ sig, int T) {
    __shared__ float win[WIN];
    __shared__ float s_b[MAXW];
    __shared__ float s_q[MAXC], s_ma[MAXC];
    __shared__ float s_pv[WTW/32];
    __shared__ int   s_pi[WTW/32];
    __shared__ int sI, sStop;
    int b = blockIdx.x;
    int dir = (b < MAXRUNS) ? 1 : 0;
    int run = dir ? b : (b - MAXRUNS);
    if (run >= g_nruns0) return;
    int tid = threadIdx.x, lane4 = tid & 3, grp = tid >> 2, wrp = tid >> 5, wl = tid & 31;
    int left = g_runL0[run], right = g_runR0[run];
    double gp = (double)__uint_as_float(g_absbits);
    long base = (long)b * CANDW;
    int cnt = 0, lastApp = INT_MIN;
    if (tid == 0) { sI = g_backup[run]; sStop = 0; }
    __syncthreads();
    while (true) {
        int i = sI;
        double f0i = (double)g_f0[i];
        double fm = f0i > 60.0 ? f0i : 60.0;
        int w = (int)__ddiv_rn(22050.0, fm);
        int s = i - w/2; if (s < 0) s = 0;
        int cl, cr;
        if (dir) {
            cl = (int)__dadd_rn((double)i, __dmul_rn(0.3,  (double)w));
            cr = (int)__dadd_rn((double)i, __dmul_rn(0.75, (double)w));
        } else {
            int a1 = (int)__dsub_rn((double)i, __dmul_rn(1.75, (double)w)); cl = a1 > 0 ? a1 : 0;
            int a2 = (int)__dsub_rn((double)i, __dmul_rn(1.3,  (double)w)); cr = a2 > 0 ? a2 : 0;
        }
        int valid = 0, nc = 0, base0 = 0;
        if (!(cl == cr || (T - cl) < w)) {
            long hi = (long)cr + w; if (hi > T) hi = T;
            nc = (int)(hi - cl - w + 1);
            valid = (nc >= 1 && nc <= MAXC && w <= MAXW && s + w <= T);
        }
        if (valid) {
            base0 = min(s, cl);
            int e1 = s + w, e2 = cl + nc - 1 + w;
            int WL = (e1 > e2 ? e1 : e2) - base0;
            if (WL > WIN) valid = 0;
            else {
                for (int k = tid; k < WL; k += WTW) win[k] = sig[base0 + k];
                __syncthreads();
                if (wrp == 0) {
                    const float* rp = win + (s - base0);
                    float psq = np_psq4(rp, w, lane4);
                    float nb = __shfl_sync(0xFFFFFFFFu, psq, 0);
                    nb = fmaxf(__fsqrt_rn(nb), 1e-12f);
                    for (int k = wl; k < w; k += 32) s_b[k] = __fdiv_rn(rp[k], nb);
                }
                __syncthreads();
                const float* cb = win + (cl - base0);
                for (int c0 = 0; c0 < nc; c0 += WTW/4) {
                    int c = c0 + grp;
                    int cc = c < nc ? c : nc - 1;
                    const float* ap = cb + cc;
                    float psq = np_psq4(ap, w, lane4);
                    float na = 0.f;
                    if (lane4 == 0) na = fmaxf(__fsqrt_rn(psq), 1e-12f);
                    na = __shfl_sync(0xFFFFFFFFu, na, 0, 4);
                    int w4 = w & ~3;
                    float acc = 0.f, ma = 0.f;
                    for (int k = lane4; k < w4; k += 4) {
                        float v = ap[k];
                        ma = fmaxf(ma, fabsf(v));
                        acc = fmaf(__fdiv_rn(v, na), s_b[k], acc);
                    }
                    float a1 = __shfl_down_sync(0xFFFFFFFFu, acc, 1, 4);
                    float ssum = __fadd_rn(acc, a1);
                    float a2 = __shfl_down_sync(0xFFFFFFFFu, ssum, 2, 4);
                    float res = __fadd_rn(ssum, a2);
                    float m1 = __shfl_down_sync(0xFFFFFFFFu, ma, 1, 4);
                    ma = fmaxf(ma, m1);
                    float m2 = __shfl_down_sync(0xFFFFFFFFu, ma, 2, 4);
                    ma = fmaxf(ma, m2);
                    if (lane4 == 0) {
                        for (int k = w4; k < w; k++) {
                            float v = ap[k];
                            ma = fmaxf(ma, fabsf(v));
                            res = fmaf(__fdiv_rn(v, na), s_b[k], res);
                        }
                        if (c < nc) { s_q[c] = res; s_ma[c] = ma; }
                    }
                }
                __syncthreads();
                {
                    float v = (tid < nc) ? s_q[tid] : -INFINITY;
                    int idx = tid;
                    for (int o = 16; o; o >>= 1) {
                        float vo = __shfl_down_sync(0xFFFFFFFFu, v, o);
                        int   io = __shfl_down_sync(0xFFFFFFFFu, idx, o);
                        if (vo > v || (vo == v && io < idx)) { v = vo; idx = io; }
                    }
                    if (wl == 0) { s_pv[wrp] = v; s_pi[wrp] = idx; }
                }
                __syncthreads();
            }
        }
        if (tid == 0) {
            double corr = -1.0, peak = 0.0;
            int stop = 0;
            if (valid) {
                float bv = s_pv[0]; int br = s_pi[0];
                for (int q = 1; q < WTW/32; q++)
                    if (s_pv[q] > bv || (s_pv[q] == bv && s_pi[q] < br)) { bv = s_pv[q]; br = s_pi[q]; }
                corr = (double)s_q[br];
                peak = (double)s_ma[br];
                i = i + (br + cl) - s;
            }
            bool neg1 = (corr == -1.0);
            if (dir) {
                if (neg1) i += w;
                if (i >= right) {
                    if (corr > 0.7 && peak > __dmul_rn(0.023333, gp)) {
                        if (cnt < CANDW) g_wci[base+cnt] = i;
                        cnt++; lastApp = i;
                    }
                    stop = 1;
                } else if (corr > 0.3 && (peak == 0.0 || peak > __dmul_rn(0.01, gp))) {
                    if (cnt < CANDW) g_wci[base+cnt] = i;
                    cnt++; lastApp = i;
                }
            } else {
                if (neg1) i -= w;
                if (i < left) {
                    if (corr > 0.7 && peak > __dmul_rn(0.023333, gp)) {
                        if (cnt < CANDW) { g_wci[base+cnt] = i; g_wcw[base+cnt] = w; }
                        cnt++;
                    }
                    stop = 1;
                } else if (corr > 0.3 && (peak == 0.0 || peak > __dmul_rn(0.01, gp))) {
                    if (cnt < CANDW) { g_wci[base+cnt] = i; g_wcw[base+cnt] = w; }
                    cnt++;
                }
            }
            sI = i; sStop = stop;
        }
        __syncthreads();
        if (sStop) break;
    }
    if (tid == 0) {
        g_wcnt[b] = min(cnt, CANDW);
        if (dir) g_lastApp[run] = lastApp;
    }
}

__global__ void K_filter() {
    __shared__ double sAR[MAXRUNS];
    int tid = threadIdx.x;
    int nr = g_nruns0;
    if (tid == 0) {
        double cur = -1e308;
        for (int r = 0; r < nr; r++) {
            sAR[r] = cur;
            if (g_lastApp[r] != INT_MIN) cur = (double)g_lastApp[r];
        }
    }
    __syncthreads();
    if (tid < nr) {
        long base = (long)(MAXRUNS + tid) * CANDW;
        int c = g_wcnt[MAXRUNS + tid], m = 0;
        double AR = sAR[tid];
        for (int j = 0; j < c; j++) {
            int i = g_wci[base + j], w = g_wcw[base + j];
            if (__dsub_rn((double)i, AR) > __dmul_rn(0.8, (double)w)) {
                g_wci[base + m] = i; m++;
            }
        }
        g_wcnt[MAXRUNS + tid] = m;
    }
}

__global__ void K_collect() {
    __shared__ int s_off[NWALK];
    int tid = threadIdx.x;
    if (tid == 0) {
        int acc = 0;
        for (int sl = 0; sl < NWALK; sl++) { s_off[sl] = acc; acc += g_wcnt[sl]; }
        g_ncand = min(acc, MAXPK);
    }
    __syncthreads();
    for (int sl = 0; sl < NWALK; sl++) {
        int c = g_wcnt[sl], o = s_off[sl];
        for (int j = tid; j < c; j += blockDim.x)
            if (o + j < MAXPK) g_cand[o+j] = g_wci[(long)sl*CANDW + j];
    }
}

__global__ void K_rank(int T) {
    int N = g_ncand;
    for (int j = blockIdx.x*blockDim.x + threadIdx.x; j < N; j += gridDim.x*blockDim.x) {
        int v = g_cand[j], rk = 0;
        for (int k = 0; k < N; k++) {
            int u = g_cand[k];
            rk += (u < v) || (u == v && k < j);
        }
        int cv = v; if (cv < 0) cv = 0; if (cv > T-1) cv = T-1;
        g_peaks[rk] = cv;
    }
    if (blockIdx.x == 0 && threadIdx.x == 0) g_npk = N;
}

__device__ int plan_run(int r, int T, double max_w, int write, int base) {
    int left_v = g_runL1[r], right_v = g_runR1[r];
    int prevR = (r == 0) ? 0 : g_runR1[r-1];
    int cnt = 0, npk = g_npk;
    if (prevR < left_v) {
        if (write && base+cnt < MAXOPS) {
            g_opd[base+cnt] = prevR; g_opsrc[base+cnt] = prevR;
            g_opl[base+cnt] = left_v - prevR; g_opn[base+cnt] = left_v - prevR;
        }
        cnt++;
    }
    while (left_v < right_v) {
        int q = dev_lb(g_peaks, npk, left_v), p;
        if (q == 0) p = 0;
        else if (q >= npk) p = dev_lb(g_peaks, npk, g_peaks[npk-1]);
        else {
            long d1 = (long)left_v - g_peaks[q-1], d2 = (long)g_peaks[q] - left_v;
            p = (d1 <= d2) ? dev_lb(g_peaks, npk, g_peaks[q-1]) : q;
        }
        double fv = (double)g_f0s[left_v];
        int period = (int)__ddiv_rn(22050.0, fv > 60.0 ? fv : 60.0);
        int left_w = period/2, right_w = period/2;
        if (p > 0) {
            long d = (long)g_peaks[p] - g_peaks[p-1];
            if ((double)d <= max_w) left_w = min((int)d, left_w);
        }
        if (p < npk-1) {
            long d = (long)g_peaks[p+1] - g_peaks[p];
            if ((double)d <= max_w) right_w = min((int)d, right_w);
        }
        int left_i = g_peaks[p] - left_w; if (left_i < 0) left_i = 0;
        int right_i = g_peaks[p] + right_w;
        int ival = (right_i - left_i) / 2;
        if (ival <= 0) break;
        long a = (long)left_v - ival;
        int seglen = min(pyslen(a, (long)left_v + ival, T),
                         pyslen(left_i, (long)left_i + 2L*ival, T));
        int Ld = pyslen(a, a + seglen, T);
        int Ls = pyslen(left_i, (long)left_i + seglen, T);
        int L = min(min(Ld, Ls), seglen);
        if (write && base+cnt < MAXOPS) {
            long as_ = a < 0 ? a + T : a;
            g_opd[base+cnt] = (int)as_; g_opsrc[base+cnt] = left_i;
            g_opl[base+cnt] = L; g_opn[base+cnt] = 2*ival;
        }
        cnt++;
        left_v += ival * 2;
    }
    return cnt;
}

__global__ void K_plan(int T) {
    __shared__ int s_cnt[MAXRUNS];
    __shared__ double s_maxw;
    int tid = threadIdx.x;
    if (tid == 0) {
        g_copy = (!g_anygate || g_npk == 0) ? 1 : 0;
        float mp = __uint_as_float(g_minbits);
        s_maxw = __ddiv_rn(27562.5, (double)mp);
        g_tail = 0; g_nops = 0;
    }
    __syncthreads();
    if (g_copy) return;
    int nr = g_nruns1;
    if (tid == 0 && nr > 0) g_tail = g_runR1[nr-1];
    if (tid < nr) s_cnt[tid] = plan_run(tid, T, s_maxw, 0, 0);
    __syncthreads();
    if (tid == 0) {
        int acc = 0;
        for (int r = 0; r < nr; r++) { int c = s_cnt[r]; s_cnt[r] = acc; acc += c; }
        g_nops = min(acc, MAXOPS);
    }
    __syncthreads();
    if (tid < nr) plan_run(tid, T, s_maxw, 1, s_cnt[tid]);
}

__global__ void K_apply(const float* __restrict__ snd, float* __restrict__ out, int T) {
    for (int b = blockIdx.x; b < g_nops; b += gridDim.x) {
        int d0 = g_opd[b], s0 = g_opsrc[b], L = g_opl[b], n = g_opn[b];
        for (int k = threadIdx.x; k < L; k += blockDim.x) {
            double ang = __ddiv_rn(__dmul_rn(6.283185307179586, (double)k), (double)n);
            float wf = (float)__dsub_rn(0.5, __dmul_rn(0.5, cos(ang)));
            atomicAdd(out + d0 + k, __fmul_rn(wf, snd[s0 + k]));
        }
    }
}

__global__ void K_tail(const float* __restrict__ snd, float* __restrict__ out, int T) {
    int t = blockIdx.x*blockDim.x + threadIdx.x;
    if (t >= T) return;
    if (g_copy || t >= g_tail) out[t] = snd[t];
}

extern "C" void kernel_launch(void* const* d_in, const int* in_sizes, int n_in,
                              void* d_out, int out_size) {
    const float* snd   = (const float*)d_in[0];
    const float* pitch = (const float*)d_in[1];
    const int*   steps = (const int*)d_in[2];
    const float* prng  = (const float*)d_in[3];
    float* out = (float*)d_out;
    int T = in_sizes[0];
    int S = in_sizes[1];

    K_init<<<1,256>>>();
    K_zero<<<GRID(T,256),256>>>(out, T);
    K_absmax<<<512,256>>>(snd, T);
    K_median<<<1,512>>>(pitch, S, steps);
    K_interp<<<GRID(T,256),256>>>(pitch, S, T);
    K_shift<<<GRID(T,256),256>>>(prng, T);
    K_mark<<<GRID(T,256),256>>>(T);
    K_sortruns<<<1,1>>>();
    K_backup<<<MAXRUNS,1>>>(snd, T);
    K_walk<<<NWALK,WTW>>>(snd, T);
    K_filter<<<1,64>>>();
    K_collect<<<1,256>>>();
    K_rank<<<64,256>>>(T);
    K_plan<<<1,64>>>(T);
    K_apply<<<2048,128>>>(snd, out, T);
    K_tail<<<GRID(T,256),256>>>(snd, out, T);
}